// round 5
// baseline (speedup 1.0000x reference)
#include <cuda_runtime.h>
#include <math.h>

// Fixed shapes: B=2048, P=4, H=16, K=48, D=4, G=64
#define PH 16
#define PK 48
#define PD 4
#define LOG2PI 1.83787706640934548356f

#define SA 66              // At row stride (floats): (i*33+g) mod 16 bijective -> conflict-free
#define SB 50              // BtB row stride: (i*25+g) mod 16 = (9i+g), 9 coprime 16 -> conflict-free
#define WPB 4              // warps (problems) per block

__device__ __forceinline__ float warp_sum(float v) {
#pragma unroll
    for (int o = 16; o > 0; o >>= 1) v += __shfl_xor_sync(0xffffffffu, v, o);
    return v;
}

// 64-length dot of two shared rows (8B aligned)
__device__ __forceinline__ float dot64(const float* p, const float* q) {
    const float2* P = reinterpret_cast<const float2*>(p);
    const float2* Q = reinterpret_cast<const float2*>(q);
    float s0 = 0.0f, s1 = 0.0f;
#pragma unroll
    for (int g = 0; g < 32; g++) {
        float2 u = P[g], v = Q[g];
        s0 = fmaf(u.x, v.x, s0);
        s1 = fmaf(u.y, v.y, s1);
    }
    return s0 + s1;
}

// 48-length dot (8B aligned)
__device__ __forceinline__ float dot48(const float* p, const float* q) {
    const float2* P = reinterpret_cast<const float2*>(p);
    const float2* Q = reinterpret_cast<const float2*>(q);
    float s0 = 0.0f, s1 = 0.0f;
#pragma unroll
    for (int g = 0; g < 24; g++) {
        float2 u = P[g], v = Q[g];
        s0 = fmaf(u.x, v.x, s0);
        s1 = fmaf(u.y, v.y, s1);
    }
    return s0 + s1;
}

__global__ __launch_bounds__(128, 6) void integ_kernel(
    const float* __restrict__ input_i,      // [BP, D]
    const float* __restrict__ Prev_coefs,   // [H, BP, H]
    const float* __restrict__ Prev_biases,  // [H, BP]
    const float* __restrict__ LP,           // [BP]
    const float* __restrict__ Log_factors,  // [BP]
    const float* __restrict__ obs_var,      // [K, BP, D]
    const float* __restrict__ hid_var,      // [K, BP, H]
    const float* __restrict__ next_var,     // [K, BP, H]
    const float* __restrict__ rec_biases,   // [K, BP]
    float* __restrict__ out, int BP)
{
    __shared__ float sAt[WPB][16 * SA];   // A^T (16 x 64); after Grams reused as N/X (17x17, stride 17)
    __shared__ float sBb[WPB][16 * SB];   // Bm^T recurrent part only (16 x 48)
    __shared__ float sBi[WPB][66];        // bias vector c (64)
    __shared__ float sMm[WPB][16 * 17];   // Gram M -> Cholesky L (col 16 = 1/diag)

    const int warp = threadIdx.x >> 5;
    const int lane = threadIdx.x & 31;
    const int prob = blockIdx.x * WPB + warp;
    if (prob >= BP) return;

    float* At   = sAt[warp];
    float* BtB  = sBb[warp];
    float* bias = sBi[warp];
    float* sM   = sMm[warp];

    const float4 xi = *reinterpret_cast<const float4*>(input_i + (size_t)prob * PD);

    // Lane owns gaussians g0 = lane, g1 = lane + 32. A rows also kept in registers.
    float a0[16], a1[16];

    if (lane < PH) {
        const float4* p = reinterpret_cast<const float4*>(
            Prev_coefs + ((size_t)lane * BP + prob) * PH);
#pragma unroll
        for (int q = 0; q < 4; q++) {
            float4 v = p[q];
            a0[4*q+0] = v.x; a0[4*q+1] = v.y; a0[4*q+2] = v.z; a0[4*q+3] = v.w;
        }
        bias[lane] = Prev_biases[(size_t)lane * BP + prob];
    } else {
        int k = lane - PH;
        const float4* p  = reinterpret_cast<const float4*>(
            hid_var + ((size_t)k * BP + prob) * PH);
        const float4* q4 = reinterpret_cast<const float4*>(
            next_var + ((size_t)k * BP + prob) * PH);
#pragma unroll
        for (int q = 0; q < 4; q++) {
            float4 v = p[q];
            a0[4*q+0] = v.x; a0[4*q+1] = v.y; a0[4*q+2] = v.z; a0[4*q+3] = v.w;
            float4 w = q4[q];
            BtB[(4*q+0)*SB + k] = w.x; BtB[(4*q+1)*SB + k] = w.y;
            BtB[(4*q+2)*SB + k] = w.z; BtB[(4*q+3)*SB + k] = w.w;
        }
        const float4 ov = *reinterpret_cast<const float4*>(
            obs_var + ((size_t)k * BP + prob) * PD);
        bias[lane] = rec_biases[(size_t)k * BP + prob]
                   + ov.x*xi.x + ov.y*xi.y + ov.z*xi.z + ov.w*xi.w;
    }
#pragma unroll
    for (int i = 0; i < 16; i++) At[i*SA + lane] = a0[i];
    {
        int k = lane + 16;   // gaussian g1 = lane + 32
        const float4* p  = reinterpret_cast<const float4*>(
            hid_var + ((size_t)k * BP + prob) * PH);
        const float4* q4 = reinterpret_cast<const float4*>(
            next_var + ((size_t)k * BP + prob) * PH);
#pragma unroll
        for (int q = 0; q < 4; q++) {
            float4 v = p[q];
            a1[4*q+0] = v.x; a1[4*q+1] = v.y; a1[4*q+2] = v.z; a1[4*q+3] = v.w;
            float4 w = q4[q];
            BtB[(4*q+0)*SB + k] = w.x; BtB[(4*q+1)*SB + k] = w.y;
            BtB[(4*q+2)*SB + k] = w.z; BtB[(4*q+3)*SB + k] = w.w;
        }
#pragma unroll
        for (int i = 0; i < 16; i++) At[i*SA + lane + 32] = a1[i];
        const float4 ov = *reinterpret_cast<const float4*>(
            obs_var + ((size_t)k * BP + prob) * PD);
        bias[lane + 32] = rec_biases[(size_t)k * BP + prob]
                        + ov.x*xi.x + ov.y*xi.y + ov.z*xi.z + ov.w*xi.w;
    }
    __syncwarp();

    // ---- M = A^T A : 136 upper-tri entries distributed over lanes ----
    for (int t = lane; t < 136; t += 32) {
        int i = 0, tt = t;
        while (tt >= 16 - i) { tt -= 16 - i; ++i; }
        int j = i + tt;
        float s = dot64(At + i*SA, At + j*SA);
        sM[i*17 + j] = s;
        if (i != j) sM[j*17 + i] = s;
    }

    // ---- column norms of [Bm|c] : lane k<17 owns column k ----
    float bn2r = 0.0f;
    if (lane < 16)       bn2r = dot48(BtB + lane*SB, BtB + lane*SB);
    else if (lane == 16) bn2r = dot64(bias, bias);

    // ---- N = A^T [Bm|c] : 272 entries into registers (At still live) ----
    float nv[9];
#pragma unroll
    for (int r = 0; r < 9; r++) {
        int t = lane + 32 * r;
        if (t < 272) {
            int i = t & 15;
            int k = t >> 4;
            nv[r] = (k < 16) ? dot48(At + i*SA + 16, BtB + k*SB)
                             : dot64(At + i*SA, bias);
        } else nv[r] = 0.0f;
    }
    __syncwarp();

    // ---- reuse At region as N/X storage (17 cols x 16, stride 17) ----
    float* sX = At;
#pragma unroll
    for (int r = 0; r < 9; r++) {
        int t = lane + 32 * r;
        if (t < 272) {
            int i = t & 15;
            int k = t >> 4;
            sX[k*17 + i] = nv[r];
        }
    }

    // ---- Cholesky M = L L^T (lane i handles row i) ----
    __syncwarp();
    for (int j = 0; j < 16; j++) {
        if (lane == j) {
            float d = sM[j*17 + j];
            for (int t = 0; t < j; t++) { float l = sM[j*17 + t]; d = fmaf(-l, l, d); }
            sM[j*17 + j] = sqrtf(d);
        }
        __syncwarp();
        float Ljj = sM[j*17 + j];
        if (lane > j && lane < 16) {
            float s = sM[lane*17 + j];
            for (int t = 0; t < j; t++) s = fmaf(-sM[lane*17 + t], sM[j*17 + t], s);
            sM[lane*17 + j] = __fdividef(s, Ljj);
        }
        __syncwarp();
    }
    if (lane < 16) sM[lane*17 + 16] = 1.0f / sM[lane*17 + lane];  // reciprocal diag
    __syncwarp();

    float lc1 = warp_sum((lane < 16) ? -__logf(sM[lane*17 + lane]) : 0.0f);

    // ---- solve M X = N per column (lane k<17); s_own = ||P col_k||^2 ----
    float s_own = 0.0f;
    if (lane < 17) {
        float y[16];
#pragma unroll
        for (int i = 0; i < 16; i++) y[i] = sX[lane*17 + i];
#pragma unroll
        for (int i = 0; i < 16; i++) {
            float s = y[i];
#pragma unroll
            for (int t = 0; t < i; t++) s = fmaf(-sM[i*17 + t], y[t], s);
            y[i] = s * sM[i*17 + 16];
        }
        float qn = 0.0f;
#pragma unroll
        for (int i = 0; i < 16; i++) qn = fmaf(y[i], y[i], qn);
        s_own = bn2r - qn;       // ||(I - Q1 Q1^T) col_k||^2
#pragma unroll
        for (int i = 15; i >= 0; i--) {
            float s = y[i];
#pragma unroll
            for (int t = i + 1; t < 16; t++) s = fmaf(-sM[t*17 + i], y[t], s);
            y[i] = s * sM[i*17 + 16];
        }
#pragma unroll
        for (int i = 0; i < 16; i++) sX[lane*17 + i] = y[i];
    }
    __syncwarp();

    // ---- projection: PB = Bm - A X, Pc = c - A x_c (into registers) ----
    float b0[16], b1[16], c0, c1;
#pragma unroll
    for (int k = 0; k < 16; k++) {
        float acc0 = (lane < 16) ? 0.0f : BtB[k*SB + lane - 16];
        float acc1 = BtB[k*SB + lane + 16];
#pragma unroll
        for (int i = 0; i < 16; i++) {
            float xv = sX[k*17 + i];            // broadcast
            acc0 = fmaf(-a0[i], xv, acc0);
            acc1 = fmaf(-a1[i], xv, acc1);
        }
        b0[k] = acc0; b1[k] = acc1;
    }
    {
        float acc0 = bias[lane];
        float acc1 = bias[lane + 32];
#pragma unroll
        for (int i = 0; i < 16; i++) {
            float xv = sX[16*17 + i];
            acc0 = fmaf(-a0[i], xv, acc0);
            acc1 = fmaf(-a1[i], xv, acc1);
        }
        c0 = acc0; c1 = acc1;
    }

    float pc2 = __shfl_sync(0xffffffffu, s_own, 16);   // ||Pc||^2

    // ---- Householder QR on PB (slarfg convention), norms downdated ----
#pragma unroll
    for (int j = 0; j < 16; j++) {
        float sj    = __shfl_sync(0xffffffffu, s_own, j);   // ||col j rows>=j||^2
        float alpha = __shfl_sync(0xffffffffu, b0[j], j);
        sj = fmaxf(sj, 1e-30f);
        float beta = -copysignf(sqrtf(sj), alpha);
        float tau  = __fdividef(beta - alpha, beta);
        float inv  = __fdividef(1.0f, alpha - beta);

        float v0 = (lane == j) ? 1.0f : ((lane > j) ? b0[j] * inv : 0.0f);
        float v1 = b1[j] * inv;

        if (lane == j)      b0[j] = beta;
        else if (lane > j)  b0[j] = 0.0f;
        b1[j] = 0.0f;

#pragma unroll
        for (int k = j + 1; k < 16; k++) {
            float w = tau * warp_sum(fmaf(v0, b0[k], v1 * b1[k]));
            b0[k] = fmaf(-w, v0, b0[k]);
            b1[k] = fmaf(-w, v1, b1[k]);
            float r = __shfl_sync(0xffffffffu, b0[k], j);   // finalized R_{j,k}
            if (lane == k) s_own = fmaf(-r, r, s_own);
        }
        float wc = tau * warp_sum(fmaf(v0, c0, v1 * c1));
        c0 = fmaf(-wc, v0, c0);
        c1 = fmaf(-wc, v1, c1);
    }

    float nb2 = warp_sum((lane < 16) ? c0 * c0 : 0.0f);
    float resid = fmaxf(pc2 - nb2, 0.0f);
    float LC = lc1 - 0.5f * ((float)(PK - PH) * LOG2PI + resid);

    // ---- outputs: Next_coefs [H,BP,H] | Next_biases [H,BP] | LP_new [BP] ----
    const size_t off1 = (size_t)PH * BP * PH;
    const size_t off2 = off1 + (size_t)PH * BP;

    if (lane < 16) {
        float4* po = reinterpret_cast<float4*>(out + ((size_t)lane * BP + prob) * PH);
        po[0] = make_float4(b0[0],  b0[1],  b0[2],  b0[3]);
        po[1] = make_float4(b0[4],  b0[5],  b0[6],  b0[7]);
        po[2] = make_float4(b0[8],  b0[9],  b0[10], b0[11]);
        po[3] = make_float4(b0[12], b0[13], b0[14], b0[15]);
        out[off1 + (size_t)lane * BP + prob] = c0;
    }
    if (lane == 0) {
        out[off2 + prob] = LP[prob] + LC + Log_factors[prob];
    }
}

extern "C" void kernel_launch(void* const* d_in, const int* in_sizes, int n_in,
                              void* d_out, int out_size) {
    const float* input_i     = (const float*)d_in[0];
    const float* Prev_coefs  = (const float*)d_in[1];
    const float* Prev_biases = (const float*)d_in[2];
    const float* LP          = (const float*)d_in[3];
    const float* Log_factors = (const float*)d_in[4];
    const float* obs_var     = (const float*)d_in[5];
    const float* hid_var     = (const float*)d_in[6];
    const float* next_var    = (const float*)d_in[7];
    const float* rec_biases  = (const float*)d_in[8];

    int BP = in_sizes[3];                     // B * P (size of LP)
    int blocks = (BP + WPB - 1) / WPB;
    integ_kernel<<<blocks, WPB * 32>>>(input_i, Prev_coefs, Prev_biases, LP, Log_factors,
                                       obs_var, hid_var, next_var, rec_biases,
                                       (float*)d_out, BP);
}

// round 6
// speedup vs baseline: 1.0544x; 1.0544x over previous
#include <cuda_runtime.h>
#include <math.h>

// Fixed shapes: B=2048, P=4, H=16, K=48, D=4, G=64
#define PH 16
#define PK 48
#define PD 4
#define LOG2PI 1.83787706640934548356f

#define SA 66              // shared row stride (floats): odd*2 -> conflict-free
#define WPB 4              // warps (problems) per block

__device__ __forceinline__ float warp_sum(float v) {
#pragma unroll
    for (int o = 16; o > 0; o >>= 1) v += __shfl_xor_sync(0xffffffffu, v, o);
    return v;
}

// 64-length dot of two shared rows (8-byte aligned, stride-66 rows => no bank conflicts)
__device__ __forceinline__ float dot64(const float* p, const float* q) {
    const float2* P = reinterpret_cast<const float2*>(p);
    const float2* Q = reinterpret_cast<const float2*>(q);
    float s0 = 0.0f, s1 = 0.0f;
#pragma unroll
    for (int g = 0; g < 32; g++) {
        float2 u = P[g], v = Q[g];
        s0 = fmaf(u.x, v.x, s0);
        s1 = fmaf(u.y, v.y, s1);
    }
    return s0 + s1;
}

// 48-length dot starting at a 64B-aligned offset (skips the 16 structural zeros)
__device__ __forceinline__ float dot48(const float* p, const float* q) {
    const float2* P = reinterpret_cast<const float2*>(p);
    const float2* Q = reinterpret_cast<const float2*>(q);
    float s0 = 0.0f, s1 = 0.0f;
#pragma unroll
    for (int g = 0; g < 24; g++) {
        float2 u = P[g], v = Q[g];
        s0 = fmaf(u.x, v.x, s0);
        s1 = fmaf(u.y, v.y, s1);
    }
    return s0 + s1;
}

__global__ __launch_bounds__(128, 5) void integ_kernel(
    const float* __restrict__ input_i,      // [BP, D]
    const float* __restrict__ Prev_coefs,   // [H, BP, H]
    const float* __restrict__ Prev_biases,  // [H, BP]
    const float* __restrict__ LP,           // [BP]
    const float* __restrict__ Log_factors,  // [BP]
    const float* __restrict__ obs_var,      // [K, BP, D]
    const float* __restrict__ hid_var,      // [K, BP, H]
    const float* __restrict__ next_var,     // [K, BP, H]
    const float* __restrict__ rec_biases,   // [K, BP]
    float* __restrict__ out, int BP)
{
    __shared__ float sAt[WPB][16 * SA];   // A^T   (16 rows x 64 gaussians)
    __shared__ float sBt[WPB][17 * SA];   // [Bm|c]^T (17 rows x 64)
    __shared__ float sMm[WPB][16 * 17];   // Gram M -> Cholesky L (col 16 = 1/diag)
    __shared__ float sXx[WPB][17 * 17];   // N -> X = M^{-1} A^T [Bm|c], column-major

    const int warp = threadIdx.x >> 5;
    const int lane = threadIdx.x & 31;
    const int prob = blockIdx.x * WPB + warp;
    if (prob >= BP) return;

    float* At = sAt[warp];
    float* Bt = sBt[warp];
    float* sM = sMm[warp];
    float* sX = sXx[warp];

    const float4 xi = *reinterpret_cast<const float4*>(input_i + (size_t)prob * PD);

    // ---- load rows into shared (lane owns gaussians g0=lane, g1=lane+32) ----
    {
        float b0[16], b1[16], c0, c1;
        if (lane < PH) {
            const float4* p = reinterpret_cast<const float4*>(
                Prev_coefs + ((size_t)lane * BP + prob) * PH);
#pragma unroll
            for (int q = 0; q < 4; q++) {
                float4 v = p[q];
                At[(4*q+0)*SA + lane] = v.x; At[(4*q+1)*SA + lane] = v.y;
                At[(4*q+2)*SA + lane] = v.z; At[(4*q+3)*SA + lane] = v.w;
            }
#pragma unroll
            for (int i = 0; i < 16; i++) b0[i] = 0.0f;
            c0 = Prev_biases[(size_t)lane * BP + prob];
        } else {
            int k = lane - PH;
            const float4* p  = reinterpret_cast<const float4*>(
                hid_var + ((size_t)k * BP + prob) * PH);
            const float4* q4 = reinterpret_cast<const float4*>(
                next_var + ((size_t)k * BP + prob) * PH);
#pragma unroll
            for (int q = 0; q < 4; q++) {
                float4 v = p[q];
                At[(4*q+0)*SA + lane] = v.x; At[(4*q+1)*SA + lane] = v.y;
                At[(4*q+2)*SA + lane] = v.z; At[(4*q+3)*SA + lane] = v.w;
                float4 w = q4[q];
                b0[4*q+0] = w.x; b0[4*q+1] = w.y; b0[4*q+2] = w.z; b0[4*q+3] = w.w;
            }
            const float4 ov = *reinterpret_cast<const float4*>(
                obs_var + ((size_t)k * BP + prob) * PD);
            c0 = rec_biases[(size_t)k * BP + prob]
               + ov.x*xi.x + ov.y*xi.y + ov.z*xi.z + ov.w*xi.w;
        }
        {
            int k = lane + (32 - PH);
            const float4* p  = reinterpret_cast<const float4*>(
                hid_var + ((size_t)k * BP + prob) * PH);
            const float4* q4 = reinterpret_cast<const float4*>(
                next_var + ((size_t)k * BP + prob) * PH);
#pragma unroll
            for (int q = 0; q < 4; q++) {
                float4 v = p[q];
                At[(4*q+0)*SA + lane + 32] = v.x; At[(4*q+1)*SA + lane + 32] = v.y;
                At[(4*q+2)*SA + lane + 32] = v.z; At[(4*q+3)*SA + lane + 32] = v.w;
                float4 w = q4[q];
                b1[4*q+0] = w.x; b1[4*q+1] = w.y; b1[4*q+2] = w.z; b1[4*q+3] = w.w;
            }
            const float4 ov = *reinterpret_cast<const float4*>(
                obs_var + ((size_t)k * BP + prob) * PD);
            c1 = rec_biases[(size_t)k * BP + prob]
               + ov.x*xi.x + ov.y*xi.y + ov.z*xi.z + ov.w*xi.w;
        }
#pragma unroll
        for (int i = 0; i < 16; i++) {
            Bt[i*SA + lane]      = b0[i];
            Bt[i*SA + lane + 32] = b1[i];
        }
        Bt[16*SA + lane]      = c0;
        Bt[16*SA + lane + 32] = c1;
    }
    __syncwarp();

    // ---- M = A^T A : 136 upper-tri entries distributed over lanes ----
    for (int t = lane; t < 136; t += 32) {
        int i = 0, tt = t;
        while (tt >= 16 - i) { tt -= 16 - i; ++i; }
        int j = i + tt;
        float s = dot64(At + i*SA, At + j*SA);
        sM[i*17 + j] = s;
        if (i != j) sM[j*17 + i] = s;
    }

    // ---- column norms of [Bm|c] : lane k<17 owns column k ----
    float bn2 = 0.0f;
    if (lane < 17) bn2 = dot64(Bt + lane*SA, Bt + lane*SA);

    // ---- N = A^T [Bm|c] : 272 entries; Bm columns skip their 16 zero rows ----
    for (int t = lane; t < 272; t += 32) {
        int i = t & 15;
        int k = t >> 4;                       // uniform per strided iteration
        sX[k*17 + i] = (k < 16)
            ? dot48(At + i*SA + 16, Bt + k*SA + 16)
            : dot64(At + i*SA, Bt + 16*SA);
    }
    __syncwarp();

    // ---- Cholesky M = L L^T (lane i handles row i) ----
    for (int j = 0; j < 16; j++) {
        if (lane == j) {
            float d = sM[j*17 + j];
            for (int t = 0; t < j; t++) { float l = sM[j*17 + t]; d = fmaf(-l, l, d); }
            sM[j*17 + j] = sqrtf(d);
        }
        __syncwarp();
        float Ljj = sM[j*17 + j];
        if (lane > j && lane < 16) {
            float s = sM[lane*17 + j];
            for (int t = 0; t < j; t++) s = fmaf(-sM[lane*17 + t], sM[j*17 + t], s);
            sM[lane*17 + j] = __fdividef(s, Ljj);
        }
        __syncwarp();
    }
    if (lane < 16) sM[lane*17 + 16] = 1.0f / sM[lane*17 + lane];  // reciprocal diag
    __syncwarp();

    float lc1 = warp_sum((lane < 16) ? -__logf(sM[lane*17 + lane]) : 0.0f);

    // ---- solve M X = N per column (lane k<17); s_own = ||P col_k||^2 via qn ----
    float s_own = 0.0f;
    if (lane < 17) {
        float y[16];
#pragma unroll
        for (int i = 0; i < 16; i++) y[i] = sX[lane*17 + i];
        // forward: y := L^{-1} N_k
#pragma unroll
        for (int i = 0; i < 16; i++) {
            float s = y[i];
#pragma unroll
            for (int t = 0; t < i; t++) s = fmaf(-sM[i*17 + t], y[t], s);
            y[i] = s * sM[i*17 + 16];
        }
        float qn = 0.0f;
#pragma unroll
        for (int i = 0; i < 16; i++) qn = fmaf(y[i], y[i], qn);
        s_own = bn2 - qn;       // ||(I - Q1 Q1^T) col_k||^2
        // backward: y := L^{-T} y
#pragma unroll
        for (int i = 15; i >= 0; i--) {
            float s = y[i];
#pragma unroll
            for (int t = i + 1; t < 16; t++) s = fmaf(-sM[t*17 + i], y[t], s);
            y[i] = s * sM[i*17 + 16];
        }
#pragma unroll
        for (int i = 0; i < 16; i++) sX[lane*17 + i] = y[i];
    }
    __syncwarp();

    // ---- projection: PB = Bm - A X, Pc = c - A x_c (back into registers) ----
    float b0[16], b1[16], c0, c1;
#pragma unroll
    for (int i = 0; i < 16; i++) {
        b0[i] = Bt[i*SA + lane];
        b1[i] = Bt[i*SA + lane + 32];
    }
    c0 = Bt[16*SA + lane];
    c1 = Bt[16*SA + lane + 32];
#pragma unroll
    for (int i = 0; i < 16; i++) {
        float ai0 = At[i*SA + lane];
        float ai1 = At[i*SA + lane + 32];
#pragma unroll
        for (int k = 0; k < 16; k++) {
            float xv = sX[k*17 + i];
            b0[k] = fmaf(-ai0, xv, b0[k]);
            b1[k] = fmaf(-ai1, xv, b1[k]);
        }
        float xc = sX[16*17 + i];
        c0 = fmaf(-ai0, xc, c0);
        c1 = fmaf(-ai1, xc, c1);
    }

    float pc2 = __shfl_sync(0xffffffffu, s_own, 16);   // ||Pc||^2

    // ---- Householder QR on PB (slarfg convention), norms downdated ----
#pragma unroll
    for (int j = 0; j < 16; j++) {
        float sj    = __shfl_sync(0xffffffffu, s_own, j);   // ||col j rows>=j||^2
        float alpha = __shfl_sync(0xffffffffu, b0[j], j);
        sj = fmaxf(sj, 1e-30f);
        float beta = -copysignf(sqrtf(sj), alpha);
        float tau  = __fdividef(beta - alpha, beta);
        float inv  = __fdividef(1.0f, alpha - beta);

        float v0 = (lane == j) ? 1.0f : ((lane > j) ? b0[j] * inv : 0.0f);
        float v1 = b1[j] * inv;

        if (lane == j)      b0[j] = beta;
        else if (lane > j)  b0[j] = 0.0f;
        b1[j] = 0.0f;

#pragma unroll
        for (int k = j + 1; k < 16; k++) {
            float w = tau * warp_sum(fmaf(v0, b0[k], v1 * b1[k]));
            b0[k] = fmaf(-w, v0, b0[k]);
            b1[k] = fmaf(-w, v1, b1[k]);
            float r = __shfl_sync(0xffffffffu, b0[k], j);   // finalized R_{j,k}
            if (lane == k) s_own = fmaf(-r, r, s_own);
        }
        float wc = tau * warp_sum(fmaf(v0, c0, v1 * c1));
        c0 = fmaf(-wc, v0, c0);
        c1 = fmaf(-wc, v1, c1);
    }

    float nb2 = warp_sum((lane < 16) ? c0 * c0 : 0.0f);
    float resid = fmaxf(pc2 - nb2, 0.0f);
    float LC = lc1 - 0.5f * ((float)(PK - PH) * LOG2PI + resid);

    // ---- outputs: Next_coefs [H,BP,H] | Next_biases [H,BP] | LP_new [BP] ----
    const size_t off1 = (size_t)PH * BP * PH;
    const size_t off2 = off1 + (size_t)PH * BP;

    if (lane < 16) {
        float4* po = reinterpret_cast<float4*>(out + ((size_t)lane * BP + prob) * PH);
        po[0] = make_float4(b0[0],  b0[1],  b0[2],  b0[3]);
        po[1] = make_float4(b0[4],  b0[5],  b0[6],  b0[7]);
        po[2] = make_float4(b0[8],  b0[9],  b0[10], b0[11]);
        po[3] = make_float4(b0[12], b0[13], b0[14], b0[15]);
        out[off1 + (size_t)lane * BP + prob] = c0;
    }
    if (lane == 0) {
        out[off2 + prob] = LP[prob] + LC + Log_factors[prob];
    }
}

extern "C" void kernel_launch(void* const* d_in, const int* in_sizes, int n_in,
                              void* d_out, int out_size) {
    const float* input_i     = (const float*)d_in[0];
    const float* Prev_coefs  = (const float*)d_in[1];
    const float* Prev_biases = (const float*)d_in[2];
    const float* LP          = (const float*)d_in[3];
    const float* Log_factors = (const float*)d_in[4];
    const float* obs_var     = (const float*)d_in[5];
    const float* hid_var     = (const float*)d_in[6];
    const float* next_var    = (const float*)d_in[7];
    const float* rec_biases  = (const float*)d_in[8];

    int BP = in_sizes[3];                     // B * P (size of LP)
    int blocks = (BP + WPB - 1) / WPB;        // 1 problem per warp, 4 warps/block
    integ_kernel<<<blocks, WPB * 32>>>(input_i, Prev_coefs, Prev_biases, LP, Log_factors,
                                       obs_var, hid_var, next_var, rec_biases,
                                       (float*)d_out, BP);
}

// round 7
// speedup vs baseline: 1.1174x; 1.0598x over previous
#include <cuda_runtime.h>
#include <math.h>

// Fixed shapes: B=2048, P=4, H=16, K=48, D=4, G=64
#define PH 16
#define PK 48
#define PD 4
#define LOG2PI 1.83787706640934548356f

#define SA 66              // shared row stride (floats): conflict-free
#define WPB 4              // warps (problems) per block

__device__ __forceinline__ float warp_sum(float v) {
#pragma unroll
    for (int o = 16; o > 0; o >>= 1) v += __shfl_xor_sync(0xffffffffu, v, o);
    return v;
}

// 64-length dot of two shared rows (8-byte aligned)
__device__ __forceinline__ float dot64(const float* p, const float* q) {
    const float2* P = reinterpret_cast<const float2*>(p);
    const float2* Q = reinterpret_cast<const float2*>(q);
    float s0 = 0.0f, s1 = 0.0f;
#pragma unroll
    for (int g = 0; g < 32; g++) {
        float2 u = P[g], v = Q[g];
        s0 = fmaf(u.x, v.x, s0);
        s1 = fmaf(u.y, v.y, s1);
    }
    return s0 + s1;
}

__global__ __launch_bounds__(128, 5) void integ_kernel(
    const float* __restrict__ input_i,      // [BP, D]
    const float* __restrict__ Prev_coefs,   // [H, BP, H]
    const float* __restrict__ Prev_biases,  // [H, BP]
    const float* __restrict__ LP,           // [BP]
    const float* __restrict__ Log_factors,  // [BP]
    const float* __restrict__ obs_var,      // [K, BP, D]
    const float* __restrict__ hid_var,      // [K, BP, H]
    const float* __restrict__ next_var,     // [K, BP, H]
    const float* __restrict__ rec_biases,   // [K, BP]
    float* __restrict__ out, int BP)
{
    __shared__ float sAt[WPB][16 * SA];   // A^T   (16 rows x 64 gaussians)
    __shared__ float sBt[WPB][17 * SA];   // [Bm|c]^T (17 rows x 64)
    __shared__ float sMm[WPB][16 * 17];   // Gram M -> Cholesky L (col 16 = 1/diag)
    __shared__ float sXx[WPB][17 * 17];   // N -> X = M^{-1} A^T [Bm|c], column-major

    const int warp = threadIdx.x >> 5;
    const int lane = threadIdx.x & 31;
    const int prob = blockIdx.x * WPB + warp;
    if (prob >= BP) return;

    float* At = sAt[warp];
    float* Bt = sBt[warp];
    float* sM = sMm[warp];
    float* sX = sXx[warp];

    const float4 xi = *reinterpret_cast<const float4*>(input_i + (size_t)prob * PD);

    // ---- load rows into shared (lane owns gaussians g0=lane, g1=lane+32) ----
    {
        float b0[16], b1[16], c0, c1;
        if (lane < PH) {
            const float4* p = reinterpret_cast<const float4*>(
                Prev_coefs + ((size_t)lane * BP + prob) * PH);
#pragma unroll
            for (int q = 0; q < 4; q++) {
                float4 v = p[q];
                At[(4*q+0)*SA + lane] = v.x; At[(4*q+1)*SA + lane] = v.y;
                At[(4*q+2)*SA + lane] = v.z; At[(4*q+3)*SA + lane] = v.w;
            }
#pragma unroll
            for (int i = 0; i < 16; i++) b0[i] = 0.0f;
            c0 = Prev_biases[(size_t)lane * BP + prob];
        } else {
            int k = lane - PH;
            const float4* p  = reinterpret_cast<const float4*>(
                hid_var + ((size_t)k * BP + prob) * PH);
            const float4* q4 = reinterpret_cast<const float4*>(
                next_var + ((size_t)k * BP + prob) * PH);
#pragma unroll
            for (int q = 0; q < 4; q++) {
                float4 v = p[q];
                At[(4*q+0)*SA + lane] = v.x; At[(4*q+1)*SA + lane] = v.y;
                At[(4*q+2)*SA + lane] = v.z; At[(4*q+3)*SA + lane] = v.w;
                float4 w = q4[q];
                b0[4*q+0] = w.x; b0[4*q+1] = w.y; b0[4*q+2] = w.z; b0[4*q+3] = w.w;
            }
            const float4 ov = *reinterpret_cast<const float4*>(
                obs_var + ((size_t)k * BP + prob) * PD);
            c0 = rec_biases[(size_t)k * BP + prob]
               + ov.x*xi.x + ov.y*xi.y + ov.z*xi.z + ov.w*xi.w;
        }
        {
            int k = lane + (32 - PH);
            const float4* p  = reinterpret_cast<const float4*>(
                hid_var + ((size_t)k * BP + prob) * PH);
            const float4* q4 = reinterpret_cast<const float4*>(
                next_var + ((size_t)k * BP + prob) * PH);
#pragma unroll
            for (int q = 0; q < 4; q++) {
                float4 v = p[q];
                At[(4*q+0)*SA + lane + 32] = v.x; At[(4*q+1)*SA + lane + 32] = v.y;
                At[(4*q+2)*SA + lane + 32] = v.z; At[(4*q+3)*SA + lane + 32] = v.w;
                float4 w = q4[q];
                b1[4*q+0] = w.x; b1[4*q+1] = w.y; b1[4*q+2] = w.z; b1[4*q+3] = w.w;
            }
            const float4 ov = *reinterpret_cast<const float4*>(
                obs_var + ((size_t)k * BP + prob) * PD);
            c1 = rec_biases[(size_t)k * BP + prob]
               + ov.x*xi.x + ov.y*xi.y + ov.z*xi.z + ov.w*xi.w;
        }
#pragma unroll
        for (int i = 0; i < 16; i++) {
            Bt[i*SA + lane]      = b0[i];
            Bt[i*SA + lane + 32] = b1[i];
        }
        Bt[16*SA + lane]      = c0;
        Bt[16*SA + lane + 32] = c1;
    }
    __syncwarp();

    // ---- M = A^T A : 2x2 register tiles; 36 tiles over 8x8 pair grid ----
#pragma unroll
    for (int rep = 0; rep < 2; rep++) {
        int t = lane + 32 * rep;
        if (t < 36) {
            int ti = 0, tt = t;
            while (tt >= 8 - ti) { tt -= 8 - ti; ++ti; }
            int tj = ti + tt;
            int i0 = 2*ti, i1 = i0 + 1, j0 = 2*tj, j1 = j0 + 1;
            const float2* Pi0 = reinterpret_cast<const float2*>(At + i0*SA);
            const float2* Pi1 = reinterpret_cast<const float2*>(At + i1*SA);
            const float2* Pj0 = reinterpret_cast<const float2*>(At + j0*SA);
            const float2* Pj1 = reinterpret_cast<const float2*>(At + j1*SA);
            float s00 = 0.0f, s01 = 0.0f, s10 = 0.0f, s11 = 0.0f;
#pragma unroll
            for (int g = 0; g < 32; g++) {
                float2 u0 = Pi0[g], u1 = Pi1[g], w0 = Pj0[g], w1 = Pj1[g];
                s00 = fmaf(u0.x, w0.x, s00); s00 = fmaf(u0.y, w0.y, s00);
                s01 = fmaf(u0.x, w1.x, s01); s01 = fmaf(u0.y, w1.y, s01);
                s10 = fmaf(u1.x, w0.x, s10); s10 = fmaf(u1.y, w0.y, s10);
                s11 = fmaf(u1.x, w1.x, s11); s11 = fmaf(u1.y, w1.y, s11);
            }
            sM[i0*17 + j0] = s00; sM[j0*17 + i0] = s00;
            sM[i0*17 + j1] = s01; sM[j1*17 + i0] = s01;
            sM[i1*17 + j0] = s10; sM[j0*17 + i1] = s10;
            sM[i1*17 + j1] = s11; sM[j1*17 + i1] = s11;
        }
    }

    // ---- column norms of [Bm|c] : lane k<17 owns column k ----
    float bn2 = 0.0f;
    if (lane < 17) bn2 = dot64(Bt + lane*SA, Bt + lane*SA);

    // ---- N = A^T Bm : 2x2 tiles over (8 i-pairs) x (8 k-pairs), zero rows skipped ----
#pragma unroll
    for (int rep = 0; rep < 2; rep++) {
        int t = lane + 32 * rep;           // 0..63, uniform tile code
        int ti = t & 7, tk = t >> 3;
        int i0 = 2*ti, i1 = i0 + 1, k0 = 2*tk, k1 = k0 + 1;
        // Bm columns are zero on gaussians 0..15 -> sum over g in [16,64)
        const float2* Pi0 = reinterpret_cast<const float2*>(At + i0*SA + 16);
        const float2* Pi1 = reinterpret_cast<const float2*>(At + i1*SA + 16);
        const float2* Qk0 = reinterpret_cast<const float2*>(Bt + k0*SA + 16);
        const float2* Qk1 = reinterpret_cast<const float2*>(Bt + k1*SA + 16);
        float s00 = 0.0f, s01 = 0.0f, s10 = 0.0f, s11 = 0.0f;
#pragma unroll
        for (int g = 0; g < 24; g++) {
            float2 u0 = Pi0[g], u1 = Pi1[g], w0 = Qk0[g], w1 = Qk1[g];
            s00 = fmaf(u0.x, w0.x, s00); s00 = fmaf(u0.y, w0.y, s00);
            s01 = fmaf(u0.x, w1.x, s01); s01 = fmaf(u0.y, w1.y, s01);
            s10 = fmaf(u1.x, w0.x, s10); s10 = fmaf(u1.y, w0.y, s10);
            s11 = fmaf(u1.x, w1.x, s11); s11 = fmaf(u1.y, w1.y, s11);
        }
        sX[k0*17 + i0] = s00; sX[k1*17 + i0] = s01;
        sX[k0*17 + i1] = s10; sX[k1*17 + i1] = s11;
    }
    // bias column k = 16 (full 64 gaussians): lanes 0..7, i-pair per lane
    if (lane < 8) {
        int i0 = 2*lane, i1 = i0 + 1;
        const float2* Pi0 = reinterpret_cast<const float2*>(At + i0*SA);
        const float2* Pi1 = reinterpret_cast<const float2*>(At + i1*SA);
        const float2* Qc  = reinterpret_cast<const float2*>(Bt + 16*SA);
        float s0 = 0.0f, s1 = 0.0f;
#pragma unroll
        for (int g = 0; g < 32; g++) {
            float2 u0 = Pi0[g], u1 = Pi1[g], w = Qc[g];
            s0 = fmaf(u0.x, w.x, s0); s0 = fmaf(u0.y, w.y, s0);
            s1 = fmaf(u1.x, w.x, s1); s1 = fmaf(u1.y, w.y, s1);
        }
        sX[16*17 + i0] = s0;
        sX[16*17 + i1] = s1;
    }
    __syncwarp();

    // ---- Cholesky M = L L^T (lane i handles row i) ----
    for (int j = 0; j < 16; j++) {
        if (lane == j) {
            float d = sM[j*17 + j];
            for (int t = 0; t < j; t++) { float l = sM[j*17 + t]; d = fmaf(-l, l, d); }
            sM[j*17 + j] = sqrtf(d);
        }
        __syncwarp();
        float Ljj = sM[j*17 + j];
        if (lane > j && lane < 16) {
            float s = sM[lane*17 + j];
            for (int t = 0; t < j; t++) s = fmaf(-sM[lane*17 + t], sM[j*17 + t], s);
            sM[lane*17 + j] = __fdividef(s, Ljj);
        }
        __syncwarp();
    }
    if (lane < 16) sM[lane*17 + 16] = 1.0f / sM[lane*17 + lane];  // reciprocal diag
    __syncwarp();

    float lc1 = warp_sum((lane < 16) ? -__logf(sM[lane*17 + lane]) : 0.0f);

    // ---- solve M X = N per column (lane k<17); s_own = ||P col_k||^2 via qn ----
    float s_own = 0.0f;
    if (lane < 17) {
        float y[16];
#pragma unroll
        for (int i = 0; i < 16; i++) y[i] = sX[lane*17 + i];
        // forward: y := L^{-1} N_k
#pragma unroll
        for (int i = 0; i < 16; i++) {
            float s = y[i];
#pragma unroll
            for (int t = 0; t < i; t++) s = fmaf(-sM[i*17 + t], y[t], s);
            y[i] = s * sM[i*17 + 16];
        }
        float qn = 0.0f;
#pragma unroll
        for (int i = 0; i < 16; i++) qn = fmaf(y[i], y[i], qn);
        s_own = bn2 - qn;       // ||(I - Q1 Q1^T) col_k||^2
        // backward: y := L^{-T} y
#pragma unroll
        for (int i = 15; i >= 0; i--) {
            float s = y[i];
#pragma unroll
            for (int t = i + 1; t < 16; t++) s = fmaf(-sM[t*17 + i], y[t], s);
            y[i] = s * sM[i*17 + 16];
        }
#pragma unroll
        for (int i = 0; i < 16; i++) sX[lane*17 + i] = y[i];
    }
    __syncwarp();

    // ---- projection: PB = Bm - A X, Pc = c - A x_c (back into registers) ----
    float b0[16], b1[16], c0, c1;
#pragma unroll
    for (int i = 0; i < 16; i++) {
        b0[i] = Bt[i*SA + lane];
        b1[i] = Bt[i*SA + lane + 32];
    }
    c0 = Bt[16*SA + lane];
    c1 = Bt[16*SA + lane + 32];
#pragma unroll
    for (int i = 0; i < 16; i++) {
        float ai0 = At[i*SA + lane];
        float ai1 = At[i*SA + lane + 32];
#pragma unroll
        for (int k = 0; k < 16; k++) {
            float xv = sX[k*17 + i];
            b0[k] = fmaf(-ai0, xv, b0[k]);
            b1[k] = fmaf(-ai1, xv, b1[k]);
        }
        float xc = sX[16*17 + i];
        c0 = fmaf(-ai0, xc, c0);
        c1 = fmaf(-ai1, xc, c1);
    }

    float pc2 = __shfl_sync(0xffffffffu, s_own, 16);   // ||Pc||^2

    // ---- Householder QR on PB (slarfg convention), norms downdated ----
#pragma unroll
    for (int j = 0; j < 16; j++) {
        float sj    = __shfl_sync(0xffffffffu, s_own, j);   // ||col j rows>=j||^2
        float alpha = __shfl_sync(0xffffffffu, b0[j], j);
        sj = fmaxf(sj, 1e-30f);
        float beta = -copysignf(sqrtf(sj), alpha);
        float tau  = __fdividef(beta - alpha, beta);
        float inv  = __fdividef(1.0f, alpha - beta);

        float v0 = (lane == j) ? 1.0f : ((lane > j) ? b0[j] * inv : 0.0f);
        float v1 = b1[j] * inv;

        if (lane == j)      b0[j] = beta;
        else if (lane > j)  b0[j] = 0.0f;
        b1[j] = 0.0f;

#pragma unroll
        for (int k = j + 1; k < 16; k++) {
            float w = tau * warp_sum(fmaf(v0, b0[k], v1 * b1[k]));
            b0[k] = fmaf(-w, v0, b0[k]);
            b1[k] = fmaf(-w, v1, b1[k]);
            float r = __shfl_sync(0xffffffffu, b0[k], j);   // finalized R_{j,k}
            if (lane == k) s_own = fmaf(-r, r, s_own);
        }
        float wc = tau * warp_sum(fmaf(v0, c0, v1 * c1));
        c0 = fmaf(-wc, v0, c0);
        c1 = fmaf(-wc, v1, c1);
    }

    float nb2 = warp_sum((lane < 16) ? c0 * c0 : 0.0f);
    float resid = fmaxf(pc2 - nb2, 0.0f);
    float LC = lc1 - 0.5f * ((float)(PK - PH) * LOG2PI + resid);

    // ---- outputs: Next_coefs [H,BP,H] | Next_biases [H,BP] | LP_new [BP] ----
    const size_t off1 = (size_t)PH * BP * PH;
    const size_t off2 = off1 + (size_t)PH * BP;

    if (lane < 16) {
        float4* po = reinterpret_cast<float4*>(out + ((size_t)lane * BP + prob) * PH);
        po[0] = make_float4(b0[0],  b0[1],  b0[2],  b0[3]);
        po[1] = make_float4(b0[4],  b0[5],  b0[6],  b0[7]);
        po[2] = make_float4(b0[8],  b0[9],  b0[10], b0[11]);
        po[3] = make_float4(b0[12], b0[13], b0[14], b0[15]);
        out[off1 + (size_t)lane * BP + prob] = c0;
    }
    if (lane == 0) {
        out[off2 + prob] = LP[prob] + LC + Log_factors[prob];
    }
}

extern "C" void kernel_launch(void* const* d_in, const int* in_sizes, int n_in,
                              void* d_out, int out_size) {
    const float* input_i     = (const float*)d_in[0];
    const float* Prev_coefs  = (const float*)d_in[1];
    const float* Prev_biases = (const float*)d_in[2];
    const float* LP          = (const float*)d_in[3];
    const float* Log_factors = (const float*)d_in[4];
    const float* obs_var     = (const float*)d_in[5];
    const float* hid_var     = (const float*)d_in[6];
    const float* next_var    = (const float*)d_in[7];
    const float* rec_biases  = (const float*)d_in[8];

    int BP = in_sizes[3];                     // B * P (size of LP)
    int blocks = (BP + WPB - 1) / WPB;        // 1 problem per warp, 4 warps/block
    integ_kernel<<<blocks, WPB * 32>>>(input_i, Prev_coefs, Prev_biases, LP, Log_factors,
                                       obs_var, hid_var, next_var, rec_biases,
                                       (float*)d_out, BP);
}

// round 8
// speedup vs baseline: 1.1967x; 1.0710x over previous
#include <cuda_runtime.h>
#include <math.h>

// Fixed shapes: B=2048, P=4, H=16, K=48, D=4, G=64
#define PH 16
#define PK 48
#define PD 4
#define LOG2PI 1.83787706640934548356f

#define SA 66              // shared row stride (floats): conflict-free
#define WPB 4              // warps (problems) per block

__device__ __forceinline__ float warp_sum(float v) {
#pragma unroll
    for (int o = 16; o > 0; o >>= 1) v += __shfl_xor_sync(0xffffffffu, v, o);
    return v;
}

// 64-length dot of two shared rows (8-byte aligned)
__device__ __forceinline__ float dot64(const float* p, const float* q) {
    const float2* P = reinterpret_cast<const float2*>(p);
    const float2* Q = reinterpret_cast<const float2*>(q);
    float s0 = 0.0f, s1 = 0.0f;
#pragma unroll
    for (int g = 0; g < 32; g++) {
        float2 u = P[g], v = Q[g];
        s0 = fmaf(u.x, v.x, s0);
        s1 = fmaf(u.y, v.y, s1);
    }
    return s0 + s1;
}

__global__ __launch_bounds__(128, 5) void integ_kernel(
    const float* __restrict__ input_i,      // [BP, D]
    const float* __restrict__ Prev_coefs,   // [H, BP, H]
    const float* __restrict__ Prev_biases,  // [H, BP]
    const float* __restrict__ LP,           // [BP]
    const float* __restrict__ Log_factors,  // [BP]
    const float* __restrict__ obs_var,      // [K, BP, D]
    const float* __restrict__ hid_var,      // [K, BP, H]
    const float* __restrict__ next_var,     // [K, BP, H]
    const float* __restrict__ rec_biases,   // [K, BP]
    float* __restrict__ out, int BP)
{
    __shared__ float sAt[WPB][16 * SA];   // A^T   (16 rows x 64 gaussians)
    __shared__ float sBt[WPB][17 * SA];   // [Bm|c]^T (17 rows x 64)
    __shared__ float sMm[WPB][16 * 17];   // Gram M -> Cholesky L (col 16 = 1/diag)
    __shared__ float sXx[WPB][17 * 17];   // N -> X = M^{-1} A^T [Bm|c], column-major

    const int warp = threadIdx.x >> 5;
    const int lane = threadIdx.x & 31;
    const int prob = blockIdx.x * WPB + warp;
    if (prob >= BP) return;

    float* At = sAt[warp];
    float* Bt = sBt[warp];
    float* sM = sMm[warp];
    float* sX = sXx[warp];

    const float4 xi = *reinterpret_cast<const float4*>(input_i + (size_t)prob * PD);

    // ---- load rows into shared (lane owns gaussians g0=lane, g1=lane+32) ----
    {
        float b0[16], b1[16], c0, c1;
        if (lane < PH) {
            const float4* p = reinterpret_cast<const float4*>(
                Prev_coefs + ((size_t)lane * BP + prob) * PH);
#pragma unroll
            for (int q = 0; q < 4; q++) {
                float4 v = p[q];
                At[(4*q+0)*SA + lane] = v.x; At[(4*q+1)*SA + lane] = v.y;
                At[(4*q+2)*SA + lane] = v.z; At[(4*q+3)*SA + lane] = v.w;
            }
#pragma unroll
            for (int i = 0; i < 16; i++) b0[i] = 0.0f;
            c0 = Prev_biases[(size_t)lane * BP + prob];
        } else {
            int k = lane - PH;
            const float4* p  = reinterpret_cast<const float4*>(
                hid_var + ((size_t)k * BP + prob) * PH);
            const float4* q4 = reinterpret_cast<const float4*>(
                next_var + ((size_t)k * BP + prob) * PH);
#pragma unroll
            for (int q = 0; q < 4; q++) {
                float4 v = p[q];
                At[(4*q+0)*SA + lane] = v.x; At[(4*q+1)*SA + lane] = v.y;
                At[(4*q+2)*SA + lane] = v.z; At[(4*q+3)*SA + lane] = v.w;
                float4 w = q4[q];
                b0[4*q+0] = w.x; b0[4*q+1] = w.y; b0[4*q+2] = w.z; b0[4*q+3] = w.w;
            }
            const float4 ov = *reinterpret_cast<const float4*>(
                obs_var + ((size_t)k * BP + prob) * PD);
            c0 = rec_biases[(size_t)k * BP + prob]
               + ov.x*xi.x + ov.y*xi.y + ov.z*xi.z + ov.w*xi.w;
        }
        {
            int k = lane + (32 - PH);
            const float4* p  = reinterpret_cast<const float4*>(
                hid_var + ((size_t)k * BP + prob) * PH);
            const float4* q4 = reinterpret_cast<const float4*>(
                next_var + ((size_t)k * BP + prob) * PH);
#pragma unroll
            for (int q = 0; q < 4; q++) {
                float4 v = p[q];
                At[(4*q+0)*SA + lane + 32] = v.x; At[(4*q+1)*SA + lane + 32] = v.y;
                At[(4*q+2)*SA + lane + 32] = v.z; At[(4*q+3)*SA + lane + 32] = v.w;
                float4 w = q4[q];
                b1[4*q+0] = w.x; b1[4*q+1] = w.y; b1[4*q+2] = w.z; b1[4*q+3] = w.w;
            }
            const float4 ov = *reinterpret_cast<const float4*>(
                obs_var + ((size_t)k * BP + prob) * PD);
            c1 = rec_biases[(size_t)k * BP + prob]
               + ov.x*xi.x + ov.y*xi.y + ov.z*xi.z + ov.w*xi.w;
        }
#pragma unroll
        for (int i = 0; i < 16; i++) {
            Bt[i*SA + lane]      = b0[i];
            Bt[i*SA + lane + 32] = b1[i];
        }
        Bt[16*SA + lane]      = c0;
        Bt[16*SA + lane + 32] = c1;
    }
    __syncwarp();

    // ---- M = A^T A : 2x2 register tiles; 36 tiles over 8x8 pair grid ----
#pragma unroll
    for (int rep = 0; rep < 2; rep++) {
        int t = lane + 32 * rep;
        if (t < 36) {
            int ti = 0, tt = t;
            while (tt >= 8 - ti) { tt -= 8 - ti; ++ti; }
            int tj = ti + tt;
            int i0 = 2*ti, i1 = i0 + 1, j0 = 2*tj, j1 = j0 + 1;
            const float2* Pi0 = reinterpret_cast<const float2*>(At + i0*SA);
            const float2* Pi1 = reinterpret_cast<const float2*>(At + i1*SA);
            const float2* Pj0 = reinterpret_cast<const float2*>(At + j0*SA);
            const float2* Pj1 = reinterpret_cast<const float2*>(At + j1*SA);
            float s00 = 0.0f, s01 = 0.0f, s10 = 0.0f, s11 = 0.0f;
#pragma unroll
            for (int g = 0; g < 32; g++) {
                float2 u0 = Pi0[g], u1 = Pi1[g], w0 = Pj0[g], w1 = Pj1[g];
                s00 = fmaf(u0.x, w0.x, s00); s00 = fmaf(u0.y, w0.y, s00);
                s01 = fmaf(u0.x, w1.x, s01); s01 = fmaf(u0.y, w1.y, s01);
                s10 = fmaf(u1.x, w0.x, s10); s10 = fmaf(u1.y, w0.y, s10);
                s11 = fmaf(u1.x, w1.x, s11); s11 = fmaf(u1.y, w1.y, s11);
            }
            sM[i0*17 + j0] = s00; sM[j0*17 + i0] = s00;
            sM[i0*17 + j1] = s01; sM[j1*17 + i0] = s01;
            sM[i1*17 + j0] = s10; sM[j0*17 + i1] = s10;
            sM[i1*17 + j1] = s11; sM[j1*17 + i1] = s11;
        }
    }

    // ---- column norms of [Bm|c] : lane k<17 owns column k ----
    float bn2 = 0.0f;
    if (lane < 17) bn2 = dot64(Bt + lane*SA, Bt + lane*SA);

    // ---- N = A^T Bm : 2x2 tiles over (8 i-pairs) x (8 k-pairs), zero rows skipped ----
#pragma unroll
    for (int rep = 0; rep < 2; rep++) {
        int t = lane + 32 * rep;           // 0..63, uniform tile code
        int ti = t & 7, tk = t >> 3;
        int i0 = 2*ti, i1 = i0 + 1, k0 = 2*tk, k1 = k0 + 1;
        // Bm columns are zero on gaussians 0..15 -> sum over g in [16,64)
        const float2* Pi0 = reinterpret_cast<const float2*>(At + i0*SA + 16);
        const float2* Pi1 = reinterpret_cast<const float2*>(At + i1*SA + 16);
        const float2* Qk0 = reinterpret_cast<const float2*>(Bt + k0*SA + 16);
        const float2* Qk1 = reinterpret_cast<const float2*>(Bt + k1*SA + 16);
        float s00 = 0.0f, s01 = 0.0f, s10 = 0.0f, s11 = 0.0f;
#pragma unroll
        for (int g = 0; g < 24; g++) {
            float2 u0 = Pi0[g], u1 = Pi1[g], w0 = Qk0[g], w1 = Qk1[g];
            s00 = fmaf(u0.x, w0.x, s00); s00 = fmaf(u0.y, w0.y, s00);
            s01 = fmaf(u0.x, w1.x, s01); s01 = fmaf(u0.y, w1.y, s01);
            s10 = fmaf(u1.x, w0.x, s10); s10 = fmaf(u1.y, w0.y, s10);
            s11 = fmaf(u1.x, w1.x, s11); s11 = fmaf(u1.y, w1.y, s11);
        }
        sX[k0*17 + i0] = s00; sX[k1*17 + i0] = s01;
        sX[k0*17 + i1] = s10; sX[k1*17 + i1] = s11;
    }
    // bias column k = 16 (full 64 gaussians): lanes 0..7, i-pair per lane
    if (lane < 8) {
        int i0 = 2*lane, i1 = i0 + 1;
        const float2* Pi0 = reinterpret_cast<const float2*>(At + i0*SA);
        const float2* Pi1 = reinterpret_cast<const float2*>(At + i1*SA);
        const float2* Qc  = reinterpret_cast<const float2*>(Bt + 16*SA);
        float s0 = 0.0f, s1 = 0.0f;
#pragma unroll
        for (int g = 0; g < 32; g++) {
            float2 u0 = Pi0[g], u1 = Pi1[g], w = Qc[g];
            s0 = fmaf(u0.x, w.x, s0); s0 = fmaf(u0.y, w.y, s0);
            s1 = fmaf(u1.x, w.x, s1); s1 = fmaf(u1.y, w.y, s1);
        }
        sX[16*17 + i0] = s0;
        sX[16*17 + i1] = s1;
    }
    __syncwarp();

    // ---- right-looking register Cholesky: lane i owns row i of M ----
    // No barriers inside: per step one broadcast shfl + sqrt/rcp + parallel
    // downdate shuffles. L columns spilled to sM for the solve; col 16 = 1/diag.
    float neglog = 0.0f;
    {
        float m[16];
        int li = lane & 15;
#pragma unroll
        for (int k = 0; k < 16; k++) m[k] = sM[li*17 + k];

#pragma unroll
        for (int j = 0; j < 16; j++) {
            float d   = __shfl_sync(0xffffffffu, m[j], j);
            float Ljj = sqrtf(d);
            float rL  = __fdividef(1.0f, Ljj);
            float lij = m[j] * rL;           // L_ij on lane i (valid for i > j)
            if (lane == j) {
                neglog = -__logf(Ljj);
                sM[j*17 + 16] = rL;          // reciprocal diag for the solve
            } else if (lane > j && lane < 16) {
                sM[lane*17 + j] = lij;       // spill column j of L
            }
#pragma unroll
            for (int k = j + 1; k < 16; k++) {
                float lkj = __shfl_sync(0xffffffffu, lij, k);
                m[k] = fmaf(-lij, lkj, m[k]);
            }
        }
    }
    float lc1 = warp_sum(neglog);
    __syncwarp();

    // ---- solve M X = N per column (lane k<17); s_own = ||P col_k||^2 via qn ----
    float s_own = 0.0f;
    if (lane < 17) {
        float y[16];
#pragma unroll
        for (int i = 0; i < 16; i++) y[i] = sX[lane*17 + i];
        // forward: y := L^{-1} N_k
#pragma unroll
        for (int i = 0; i < 16; i++) {
            float s = y[i];
#pragma unroll
            for (int t = 0; t < i; t++) s = fmaf(-sM[i*17 + t], y[t], s);
            y[i] = s * sM[i*17 + 16];
        }
        float qn = 0.0f;
#pragma unroll
        for (int i = 0; i < 16; i++) qn = fmaf(y[i], y[i], qn);
        s_own = bn2 - qn;       // ||(I - Q1 Q1^T) col_k||^2
        // backward: y := L^{-T} y
#pragma unroll
        for (int i = 15; i >= 0; i--) {
            float s = y[i];
#pragma unroll
            for (int t = i + 1; t < 16; t++) s = fmaf(-sM[t*17 + i], y[t], s);
            y[i] = s * sM[i*17 + 16];
        }
#pragma unroll
        for (int i = 0; i < 16; i++) sX[lane*17 + i] = y[i];
    }
    __syncwarp();

    // ---- projection: PB = Bm - A X, Pc = c - A x_c (back into registers) ----
    float b0[16], b1[16], c0, c1;
#pragma unroll
    for (int i = 0; i < 16; i++) {
        b0[i] = Bt[i*SA + lane];
        b1[i] = Bt[i*SA + lane + 32];
    }
    c0 = Bt[16*SA + lane];
    c1 = Bt[16*SA + lane + 32];
#pragma unroll
    for (int i = 0; i < 16; i++) {
        float ai0 = At[i*SA + lane];
        float ai1 = At[i*SA + lane + 32];
#pragma unroll
        for (int k = 0; k < 16; k++) {
            float xv = sX[k*17 + i];
            b0[k] = fmaf(-ai0, xv, b0[k]);
            b1[k] = fmaf(-ai1, xv, b1[k]);
        }
        float xc = sX[16*17 + i];
        c0 = fmaf(-ai0, xc, c0);
        c1 = fmaf(-ai1, xc, c1);
    }

    float pc2 = __shfl_sync(0xffffffffu, s_own, 16);   // ||Pc||^2

    // ---- Householder QR on PB (slarfg convention), norms downdated ----
#pragma unroll
    for (int j = 0; j < 16; j++) {
        float sj    = __shfl_sync(0xffffffffu, s_own, j);   // ||col j rows>=j||^2
        float alpha = __shfl_sync(0xffffffffu, b0[j], j);
        sj = fmaxf(sj, 1e-30f);
        float beta = -copysignf(sqrtf(sj), alpha);
        float tau  = __fdividef(beta - alpha, beta);
        float inv  = __fdividef(1.0f, alpha - beta);

        float v0 = (lane == j) ? 1.0f : ((lane > j) ? b0[j] * inv : 0.0f);
        float v1 = b1[j] * inv;

        if (lane == j)      b0[j] = beta;
        else if (lane > j)  b0[j] = 0.0f;
        b1[j] = 0.0f;

#pragma unroll
        for (int k = j + 1; k < 16; k++) {
            float w = tau * warp_sum(fmaf(v0, b0[k], v1 * b1[k]));
            b0[k] = fmaf(-w, v0, b0[k]);
            b1[k] = fmaf(-w, v1, b1[k]);
            float r = __shfl_sync(0xffffffffu, b0[k], j);   // finalized R_{j,k}
            if (lane == k) s_own = fmaf(-r, r, s_own);
        }
        float wc = tau * warp_sum(fmaf(v0, c0, v1 * c1));
        c0 = fmaf(-wc, v0, c0);
        c1 = fmaf(-wc, v1, c1);
    }

    float nb2 = warp_sum((lane < 16) ? c0 * c0 : 0.0f);
    float resid = fmaxf(pc2 - nb2, 0.0f);
    float LC = lc1 - 0.5f * ((float)(PK - PH) * LOG2PI + resid);

    // ---- outputs: Next_coefs [H,BP,H] | Next_biases [H,BP] | LP_new [BP] ----
    const size_t off1 = (size_t)PH * BP * PH;
    const size_t off2 = off1 + (size_t)PH * BP;

    if (lane < 16) {
        float4* po = reinterpret_cast<float4*>(out + ((size_t)lane * BP + prob) * PH);
        po[0] = make_float4(b0[0],  b0[1],  b0[2],  b0[3]);
        po[1] = make_float4(b0[4],  b0[5],  b0[6],  b0[7]);
        po[2] = make_float4(b0[8],  b0[9],  b0[10], b0[11]);
        po[3] = make_float4(b0[12], b0[13], b0[14], b0[15]);
        out[off1 + (size_t)lane * BP + prob] = c0;
    }
    if (lane == 0) {
        out[off2 + prob] = LP[prob] + LC + Log_factors[prob];
    }
}

extern "C" void kernel_launch(void* const* d_in, const int* in_sizes, int n_in,
                              void* d_out, int out_size) {
    const float* input_i     = (const float*)d_in[0];
    const float* Prev_coefs  = (const float*)d_in[1];
    const float* Prev_biases = (const float*)d_in[2];
    const float* LP          = (const float*)d_in[3];
    const float* Log_factors = (const float*)d_in[4];
    const float* obs_var     = (const float*)d_in[5];
    const float* hid_var     = (const float*)d_in[6];
    const float* next_var    = (const float*)d_in[7];
    const float* rec_biases  = (const float*)d_in[8];

    int BP = in_sizes[3];                     // B * P (size of LP)
    int blocks = (BP + WPB - 1) / WPB;        // 1 problem per warp, 4 warps/block
    integ_kernel<<<blocks, WPB * 32>>>(input_i, Prev_coefs, Prev_biases, LP, Log_factors,
                                       obs_var, hid_var, next_var, rec_biases,
                                       (float*)d_out, BP);
}

// round 9
// speedup vs baseline: 1.2980x; 1.0846x over previous
#include <cuda_runtime.h>
#include <math.h>

// Fixed shapes: B=2048, P=4, H=16, K=48, D=4, G=64
#define PH 16
#define PK 48
#define PD 4
#define LOG2PI 1.83787706640934548356f

#define SA 66              // shared row stride (floats): conflict-free
#define WPB 4              // warps (problems) per block

__device__ __forceinline__ float warp_sum(float v) {
#pragma unroll
    for (int o = 16; o > 0; o >>= 1) v += __shfl_xor_sync(0xffffffffu, v, o);
    return v;
}

// 64-length dot of two shared rows (8-byte aligned)
__device__ __forceinline__ float dot64(const float* p, const float* q) {
    const float2* P = reinterpret_cast<const float2*>(p);
    const float2* Q = reinterpret_cast<const float2*>(q);
    float s0 = 0.0f, s1 = 0.0f;
#pragma unroll
    for (int g = 0; g < 32; g++) {
        float2 u = P[g], v = Q[g];
        s0 = fmaf(u.x, v.x, s0);
        s1 = fmaf(u.y, v.y, s1);
    }
    return s0 + s1;
}

__global__ __launch_bounds__(128, 5) void integ_kernel(
    const float* __restrict__ input_i,      // [BP, D]
    const float* __restrict__ Prev_coefs,   // [H, BP, H]
    const float* __restrict__ Prev_biases,  // [H, BP]
    const float* __restrict__ LP,           // [BP]
    const float* __restrict__ Log_factors,  // [BP]
    const float* __restrict__ obs_var,      // [K, BP, D]
    const float* __restrict__ hid_var,      // [K, BP, H]
    const float* __restrict__ next_var,     // [K, BP, H]
    const float* __restrict__ rec_biases,   // [K, BP]
    float* __restrict__ out, int BP)
{
    __shared__ float sAt[WPB][16 * SA];   // A^T   (16 rows x 64 gaussians)
    __shared__ float sBt[WPB][17 * SA];   // [Bm|c]^T (17 rows x 64)
    __shared__ float sMm[WPB][16 * 17];   // Gram M -> Cholesky L (col 16 = 1/diag)
    __shared__ float sXx[WPB][17 * 17];   // N -> X = M^{-1} A^T [Bm|c], column-major

    const int warp = threadIdx.x >> 5;
    const int lane = threadIdx.x & 31;
    const int prob = blockIdx.x * WPB + warp;
    if (prob >= BP) return;

    float* At = sAt[warp];
    float* Bt = sBt[warp];
    float* sM = sMm[warp];
    float* sX = sXx[warp];

    const float4 xi = *reinterpret_cast<const float4*>(input_i + (size_t)prob * PD);

    // ---- load rows into shared (lane owns gaussians g0=lane, g1=lane+32) ----
    {
        float b0[16], b1[16], c0, c1;
        if (lane < PH) {
            const float4* p = reinterpret_cast<const float4*>(
                Prev_coefs + ((size_t)lane * BP + prob) * PH);
#pragma unroll
            for (int q = 0; q < 4; q++) {
                float4 v = p[q];
                At[(4*q+0)*SA + lane] = v.x; At[(4*q+1)*SA + lane] = v.y;
                At[(4*q+2)*SA + lane] = v.z; At[(4*q+3)*SA + lane] = v.w;
            }
#pragma unroll
            for (int i = 0; i < 16; i++) b0[i] = 0.0f;
            c0 = Prev_biases[(size_t)lane * BP + prob];
        } else {
            int k = lane - PH;
            const float4* p  = reinterpret_cast<const float4*>(
                hid_var + ((size_t)k * BP + prob) * PH);
            const float4* q4 = reinterpret_cast<const float4*>(
                next_var + ((size_t)k * BP + prob) * PH);
#pragma unroll
            for (int q = 0; q < 4; q++) {
                float4 v = p[q];
                At[(4*q+0)*SA + lane] = v.x; At[(4*q+1)*SA + lane] = v.y;
                At[(4*q+2)*SA + lane] = v.z; At[(4*q+3)*SA + lane] = v.w;
                float4 w = q4[q];
                b0[4*q+0] = w.x; b0[4*q+1] = w.y; b0[4*q+2] = w.z; b0[4*q+3] = w.w;
            }
            const float4 ov = *reinterpret_cast<const float4*>(
                obs_var + ((size_t)k * BP + prob) * PD);
            c0 = rec_biases[(size_t)k * BP + prob]
               + ov.x*xi.x + ov.y*xi.y + ov.z*xi.z + ov.w*xi.w;
        }
        {
            int k = lane + (32 - PH);
            const float4* p  = reinterpret_cast<const float4*>(
                hid_var + ((size_t)k * BP + prob) * PH);
            const float4* q4 = reinterpret_cast<const float4*>(
                next_var + ((size_t)k * BP + prob) * PH);
#pragma unroll
            for (int q = 0; q < 4; q++) {
                float4 v = p[q];
                At[(4*q+0)*SA + lane + 32] = v.x; At[(4*q+1)*SA + lane + 32] = v.y;
                At[(4*q+2)*SA + lane + 32] = v.z; At[(4*q+3)*SA + lane + 32] = v.w;
                float4 w = q4[q];
                b1[4*q+0] = w.x; b1[4*q+1] = w.y; b1[4*q+2] = w.z; b1[4*q+3] = w.w;
            }
            const float4 ov = *reinterpret_cast<const float4*>(
                obs_var + ((size_t)k * BP + prob) * PD);
            c1 = rec_biases[(size_t)k * BP + prob]
               + ov.x*xi.x + ov.y*xi.y + ov.z*xi.z + ov.w*xi.w;
        }
#pragma unroll
        for (int i = 0; i < 16; i++) {
            Bt[i*SA + lane]      = b0[i];
            Bt[i*SA + lane + 32] = b1[i];
        }
        Bt[16*SA + lane]      = c0;
        Bt[16*SA + lane + 32] = c1;
    }
    __syncwarp();

    // ---- M = A^T A : 2x2 register tiles; 36 tiles over 8x8 pair grid ----
#pragma unroll
    for (int rep = 0; rep < 2; rep++) {
        int t = lane + 32 * rep;
        if (t < 36) {
            int ti = 0, tt = t;
            while (tt >= 8 - ti) { tt -= 8 - ti; ++ti; }
            int tj = ti + tt;
            int i0 = 2*ti, i1 = i0 + 1, j0 = 2*tj, j1 = j0 + 1;
            const float2* Pi0 = reinterpret_cast<const float2*>(At + i0*SA);
            const float2* Pi1 = reinterpret_cast<const float2*>(At + i1*SA);
            const float2* Pj0 = reinterpret_cast<const float2*>(At + j0*SA);
            const float2* Pj1 = reinterpret_cast<const float2*>(At + j1*SA);
            float s00 = 0.0f, s01 = 0.0f, s10 = 0.0f, s11 = 0.0f;
#pragma unroll
            for (int g = 0; g < 32; g++) {
                float2 u0 = Pi0[g], u1 = Pi1[g], w0 = Pj0[g], w1 = Pj1[g];
                s00 = fmaf(u0.x, w0.x, s00); s00 = fmaf(u0.y, w0.y, s00);
                s01 = fmaf(u0.x, w1.x, s01); s01 = fmaf(u0.y, w1.y, s01);
                s10 = fmaf(u1.x, w0.x, s10); s10 = fmaf(u1.y, w0.y, s10);
                s11 = fmaf(u1.x, w1.x, s11); s11 = fmaf(u1.y, w1.y, s11);
            }
            sM[i0*17 + j0] = s00; sM[j0*17 + i0] = s00;
            sM[i0*17 + j1] = s01; sM[j1*17 + i0] = s01;
            sM[i1*17 + j0] = s10; sM[j0*17 + i1] = s10;
            sM[i1*17 + j1] = s11; sM[j1*17 + i1] = s11;
        }
    }
    __syncwarp();

    // ==== ONE barrier-free region: N-Gram + bn2 (throughput) overlapped with
    //      the register Cholesky (latency chain). They are independent. ====

    // ---- N = A^T Bm : 2x2 tiles over (8 i-pairs) x (8 k-pairs), zero rows skipped ----
#pragma unroll
    for (int rep = 0; rep < 2; rep++) {
        int t = lane + 32 * rep;           // 0..63, uniform tile code
        int ti = t & 7, tk = t >> 3;
        int i0 = 2*ti, i1 = i0 + 1, k0 = 2*tk, k1 = k0 + 1;
        // Bm columns are zero on gaussians 0..15 -> sum over g in [16,64)
        const float2* Pi0 = reinterpret_cast<const float2*>(At + i0*SA + 16);
        const float2* Pi1 = reinterpret_cast<const float2*>(At + i1*SA + 16);
        const float2* Qk0 = reinterpret_cast<const float2*>(Bt + k0*SA + 16);
        const float2* Qk1 = reinterpret_cast<const float2*>(Bt + k1*SA + 16);
        float s00 = 0.0f, s01 = 0.0f, s10 = 0.0f, s11 = 0.0f;
#pragma unroll
        for (int g = 0; g < 24; g++) {
            float2 u0 = Pi0[g], u1 = Pi1[g], w0 = Qk0[g], w1 = Qk1[g];
            s00 = fmaf(u0.x, w0.x, s00); s00 = fmaf(u0.y, w0.y, s00);
            s01 = fmaf(u0.x, w1.x, s01); s01 = fmaf(u0.y, w1.y, s01);
            s10 = fmaf(u1.x, w0.x, s10); s10 = fmaf(u1.y, w0.y, s10);
            s11 = fmaf(u1.x, w1.x, s11); s11 = fmaf(u1.y, w1.y, s11);
        }
        sX[k0*17 + i0] = s00; sX[k1*17 + i0] = s01;
        sX[k0*17 + i1] = s10; sX[k1*17 + i1] = s11;
    }
    // bias column k = 16 (full 64 gaussians): lanes 0..7, i-pair per lane
    if (lane < 8) {
        int i0 = 2*lane, i1 = i0 + 1;
        const float2* Pi0 = reinterpret_cast<const float2*>(At + i0*SA);
        const float2* Pi1 = reinterpret_cast<const float2*>(At + i1*SA);
        const float2* Qc  = reinterpret_cast<const float2*>(Bt + 16*SA);
        float s0 = 0.0f, s1 = 0.0f;
#pragma unroll
        for (int g = 0; g < 32; g++) {
            float2 u0 = Pi0[g], u1 = Pi1[g], w = Qc[g];
            s0 = fmaf(u0.x, w.x, s0); s0 = fmaf(u0.y, w.y, s0);
            s1 = fmaf(u1.x, w.x, s1); s1 = fmaf(u1.y, w.y, s1);
        }
        sX[16*17 + i0] = s0;
        sX[16*17 + i1] = s1;
    }

    // ---- column norms of [Bm|c] : lane k<17 owns column k ----
    float bn2 = 0.0f;
    if (lane < 17) bn2 = dot64(Bt + lane*SA, Bt + lane*SA);

    // ---- right-looking register Cholesky: lane i owns row i of M ----
    float neglog = 0.0f;
    {
        float m[16];
        int li = lane & 15;
#pragma unroll
        for (int k = 0; k < 16; k++) m[k] = sM[li*17 + k];

#pragma unroll
        for (int j = 0; j < 16; j++) {
            float d   = __shfl_sync(0xffffffffu, m[j], j);
            float Ljj = sqrtf(d);
            float rL  = __fdividef(1.0f, Ljj);
            float lij = m[j] * rL;           // L_ij on lane i (valid for i > j)
            if (lane == j) {
                neglog = -__logf(Ljj);
                sM[j*17 + 16] = rL;          // reciprocal diag for the solve
            } else if (lane > j && lane < 16) {
                sM[lane*17 + j] = lij;       // spill column j of L
            }
#pragma unroll
            for (int k = j + 1; k < 16; k++) {
                float lkj = __shfl_sync(0xffffffffu, lij, k);
                m[k] = fmaf(-lij, lkj, m[k]);
            }
        }
    }
    __syncwarp();

    // ---- solve M X = N per column (lane k<17); s_own = ||P col_k||^2 via qn ----
    // Inner sums parity-split (short dependence chains); freshest y consumed last.
    float s_own = 0.0f;
    if (lane < 17) {
        float y[16];
#pragma unroll
        for (int i = 0; i < 16; i++) y[i] = sX[lane*17 + i];
        // forward: y := L^{-1} N_k  (ascending t: t=i-1 lands last)
#pragma unroll
        for (int i = 0; i < 16; i++) {
            float p0 = 0.0f, p1 = 0.0f;
#pragma unroll
            for (int t = 0; t < i; t++) {
                if (t & 1) p1 = fmaf(sM[i*17 + t], y[t], p1);
                else       p0 = fmaf(sM[i*17 + t], y[t], p0);
            }
            y[i] = (y[i] - (p0 + p1)) * sM[i*17 + 16];
        }
        float qn = 0.0f;
#pragma unroll
        for (int i = 0; i < 16; i++) qn = fmaf(y[i], y[i], qn);
        s_own = bn2 - qn;       // ||(I - Q1 Q1^T) col_k||^2
        // backward: y := L^{-T} y  (descending t: t=i+1 lands last)
#pragma unroll
        for (int i = 15; i >= 0; i--) {
            float p0 = 0.0f, p1 = 0.0f;
#pragma unroll
            for (int t = 15; t > i; t--) {
                if (t & 1) p1 = fmaf(sM[t*17 + i], y[t], p1);
                else       p0 = fmaf(sM[t*17 + i], y[t], p0);
            }
            y[i] = (y[i] - (p0 + p1)) * sM[i*17 + 16];
        }
#pragma unroll
        for (int i = 0; i < 16; i++) sX[lane*17 + i] = y[i];
    }
    __syncwarp();

    // ---- projection: PB = Bm - A X, Pc = c - A x_c (back into registers) ----
    float b0[16], b1[16], c0, c1;
#pragma unroll
    for (int i = 0; i < 16; i++) {
        b0[i] = Bt[i*SA + lane];
        b1[i] = Bt[i*SA + lane + 32];
    }
    c0 = Bt[16*SA + lane];
    c1 = Bt[16*SA + lane + 32];
#pragma unroll
    for (int i = 0; i < 16; i++) {
        float ai0 = At[i*SA + lane];
        float ai1 = At[i*SA + lane + 32];
#pragma unroll
        for (int k = 0; k < 16; k++) {
            float xv = sX[k*17 + i];
            b0[k] = fmaf(-ai0, xv, b0[k]);
            b1[k] = fmaf(-ai1, xv, b1[k]);
        }
        float xc = sX[16*17 + i];
        c0 = fmaf(-ai0, xc, c0);
        c1 = fmaf(-ai1, xc, c1);
    }

    float pc2 = __shfl_sync(0xffffffffu, s_own, 16);   // ||Pc||^2

    // ---- Householder QR on PB (slarfg convention), norms downdated ----
#pragma unroll
    for (int j = 0; j < 16; j++) {
        float sj    = __shfl_sync(0xffffffffu, s_own, j);   // ||col j rows>=j||^2
        float alpha = __shfl_sync(0xffffffffu, b0[j], j);
        sj = fmaxf(sj, 1e-30f);
        float beta = -copysignf(sqrtf(sj), alpha);
        float tau  = __fdividef(beta - alpha, beta);
        float inv  = __fdividef(1.0f, alpha - beta);

        float v0 = (lane == j) ? 1.0f : ((lane > j) ? b0[j] * inv : 0.0f);
        float v1 = b1[j] * inv;

        if (lane == j)      b0[j] = beta;
        else if (lane > j)  b0[j] = 0.0f;
        b1[j] = 0.0f;

#pragma unroll
        for (int k = j + 1; k < 16; k++) {
            float w = tau * warp_sum(fmaf(v0, b0[k], v1 * b1[k]));
            b0[k] = fmaf(-w, v0, b0[k]);
            b1[k] = fmaf(-w, v1, b1[k]);
            float r = __shfl_sync(0xffffffffu, b0[k], j);   // finalized R_{j,k}
            if (lane == k) s_own = fmaf(-r, r, s_own);
        }
        float wc = tau * warp_sum(fmaf(v0, c0, v1 * c1));
        c0 = fmaf(-wc, v0, c0);
        c1 = fmaf(-wc, v1, c1);
    }

    float lc1 = warp_sum(neglog);                       // deferred off the hot chain
    float nb2 = warp_sum((lane < 16) ? c0 * c0 : 0.0f);
    float resid = fmaxf(pc2 - nb2, 0.0f);
    float LC = lc1 - 0.5f * ((float)(PK - PH) * LOG2PI + resid);

    // ---- outputs: Next_coefs [H,BP,H] | Next_biases [H,BP] | LP_new [BP] ----
    const size_t off1 = (size_t)PH * BP * PH;
    const size_t off2 = off1 + (size_t)PH * BP;

    if (lane < 16) {
        float4* po = reinterpret_cast<float4*>(out + ((size_t)lane * BP + prob) * PH);
        po[0] = make_float4(b0[0],  b0[1],  b0[2],  b0[3]);
        po[1] = make_float4(b0[4],  b0[5],  b0[6],  b0[7]);
        po[2] = make_float4(b0[8],  b0[9],  b0[10], b0[11]);
        po[3] = make_float4(b0[12], b0[13], b0[14], b0[15]);
        out[off1 + (size_t)lane * BP + prob] = c0;
    }
    if (lane == 0) {
        out[off2 + prob] = LP[prob] + LC + Log_factors[prob];
    }
}

extern "C" void kernel_launch(void* const* d_in, const int* in_sizes, int n_in,
                              void* d_out, int out_size) {
    const float* input_i     = (const float*)d_in[0];
    const float* Prev_coefs  = (const float*)d_in[1];
    const float* Prev_biases = (const float*)d_in[2];
    const float* LP          = (const float*)d_in[3];
    const float* Log_factors = (const float*)d_in[4];
    const float* obs_var     = (const float*)d_in[5];
    const float* hid_var     = (const float*)d_in[6];
    const float* next_var    = (const float*)d_in[7];
    const float* rec_biases  = (const float*)d_in[8];

    int BP = in_sizes[3];                     // B * P (size of LP)
    int blocks = (BP + WPB - 1) / WPB;        // 1 problem per warp, 4 warps/block
    integ_kernel<<<blocks, WPB * 32>>>(input_i, Prev_coefs, Prev_biases, LP, Log_factors,
                                       obs_var, hid_var, next_var, rec_biases,
                                       (float*)d_out, BP);
}

// round 10
// speedup vs baseline: 1.5451x; 1.1904x over previous
#include <cuda_runtime.h>
#include <math.h>

// Fixed shapes: B=2048, P=4, H=16, K=48, D=4, G=64
#define PH 16
#define PK 48
#define PD 4
#define LOG2PI 1.83787706640934548356f

#define SA 66              // shared row stride (floats): conflict-free
#define WPB 4              // warps (problems) per block

__device__ __forceinline__ float warp_sum(float v) {
#pragma unroll
    for (int o = 16; o > 0; o >>= 1) v += __shfl_xor_sync(0xffffffffu, v, o);
    return v;
}

// Two interleaved butterfly reductions: forces 2 independent SHFL chains in flight.
__device__ __forceinline__ void warp_sum2(float& a, float& b) {
#pragma unroll
    for (int o = 16; o > 0; o >>= 1) {
        float ta = __shfl_xor_sync(0xffffffffu, a, o);
        float tb = __shfl_xor_sync(0xffffffffu, b, o);
        a += ta;
        b += tb;
    }
}

// 64-length dot of two shared rows (8-byte aligned)
__device__ __forceinline__ float dot64(const float* p, const float* q) {
    const float2* P = reinterpret_cast<const float2*>(p);
    const float2* Q = reinterpret_cast<const float2*>(q);
    float s0 = 0.0f, s1 = 0.0f;
#pragma unroll
    for (int g = 0; g < 32; g++) {
        float2 u = P[g], v = Q[g];
        s0 = fmaf(u.x, v.x, s0);
        s1 = fmaf(u.y, v.y, s1);
    }
    return s0 + s1;
}

__global__ __launch_bounds__(128, 5) void integ_kernel(
    const float* __restrict__ input_i,      // [BP, D]
    const float* __restrict__ Prev_coefs,   // [H, BP, H]
    const float* __restrict__ Prev_biases,  // [H, BP]
    const float* __restrict__ LP,           // [BP]
    const float* __restrict__ Log_factors,  // [BP]
    const float* __restrict__ obs_var,      // [K, BP, D]
    const float* __restrict__ hid_var,      // [K, BP, H]
    const float* __restrict__ next_var,     // [K, BP, H]
    const float* __restrict__ rec_biases,   // [K, BP]
    float* __restrict__ out, int BP)
{
    __shared__ float sAt[WPB][16 * SA];   // A^T   (16 rows x 64 gaussians)
    __shared__ float sBt[WPB][17 * SA];   // [Bm|c]^T (17 rows x 64)
    __shared__ float sMm[WPB][16 * 17];   // Gram M -> Cholesky L (col 16 = 1/diag)
    __shared__ float sXx[WPB][17 * 17];   // N -> X = M^{-1} A^T [Bm|c], column-major

    const int warp = threadIdx.x >> 5;
    const int lane = threadIdx.x & 31;
    const int prob = blockIdx.x * WPB + warp;
    if (prob >= BP) return;

    float* At = sAt[warp];
    float* Bt = sBt[warp];
    float* sM = sMm[warp];
    float* sX = sXx[warp];

    const float4 xi = *reinterpret_cast<const float4*>(input_i + (size_t)prob * PD);

    // ---- load rows into shared (lane owns gaussians g0=lane, g1=lane+32) ----
    {
        float b0[16], b1[16], c0, c1;
        if (lane < PH) {
            const float4* p = reinterpret_cast<const float4*>(
                Prev_coefs + ((size_t)lane * BP + prob) * PH);
#pragma unroll
            for (int q = 0; q < 4; q++) {
                float4 v = p[q];
                At[(4*q+0)*SA + lane] = v.x; At[(4*q+1)*SA + lane] = v.y;
                At[(4*q+2)*SA + lane] = v.z; At[(4*q+3)*SA + lane] = v.w;
            }
#pragma unroll
            for (int i = 0; i < 16; i++) b0[i] = 0.0f;
            c0 = Prev_biases[(size_t)lane * BP + prob];
        } else {
            int k = lane - PH;
            const float4* p  = reinterpret_cast<const float4*>(
                hid_var + ((size_t)k * BP + prob) * PH);
            const float4* q4 = reinterpret_cast<const float4*>(
                next_var + ((size_t)k * BP + prob) * PH);
#pragma unroll
            for (int q = 0; q < 4; q++) {
                float4 v = p[q];
                At[(4*q+0)*SA + lane] = v.x; At[(4*q+1)*SA + lane] = v.y;
                At[(4*q+2)*SA + lane] = v.z; At[(4*q+3)*SA + lane] = v.w;
                float4 w = q4[q];
                b0[4*q+0] = w.x; b0[4*q+1] = w.y; b0[4*q+2] = w.z; b0[4*q+3] = w.w;
            }
            const float4 ov = *reinterpret_cast<const float4*>(
                obs_var + ((size_t)k * BP + prob) * PD);
            c0 = rec_biases[(size_t)k * BP + prob]
               + ov.x*xi.x + ov.y*xi.y + ov.z*xi.z + ov.w*xi.w;
        }
        {
            int k = lane + (32 - PH);
            const float4* p  = reinterpret_cast<const float4*>(
                hid_var + ((size_t)k * BP + prob) * PH);
            const float4* q4 = reinterpret_cast<const float4*>(
                next_var + ((size_t)k * BP + prob) * PH);
#pragma unroll
            for (int q = 0; q < 4; q++) {
                float4 v = p[q];
                At[(4*q+0)*SA + lane + 32] = v.x; At[(4*q+1)*SA + lane + 32] = v.y;
                At[(4*q+2)*SA + lane + 32] = v.z; At[(4*q+3)*SA + lane + 32] = v.w;
                float4 w = q4[q];
                b1[4*q+0] = w.x; b1[4*q+1] = w.y; b1[4*q+2] = w.z; b1[4*q+3] = w.w;
            }
            const float4 ov = *reinterpret_cast<const float4*>(
                obs_var + ((size_t)k * BP + prob) * PD);
            c1 = rec_biases[(size_t)k * BP + prob]
               + ov.x*xi.x + ov.y*xi.y + ov.z*xi.z + ov.w*xi.w;
        }
#pragma unroll
        for (int i = 0; i < 16; i++) {
            Bt[i*SA + lane]      = b0[i];
            Bt[i*SA + lane + 32] = b1[i];
        }
        Bt[16*SA + lane]      = c0;
        Bt[16*SA + lane + 32] = c1;
    }
    __syncwarp();

    // ---- M = A^T A : 2x2 register tiles; 36 tiles over 8x8 pair grid ----
#pragma unroll
    for (int rep = 0; rep < 2; rep++) {
        int t = lane + 32 * rep;
        if (t < 36) {
            int ti = 0, tt = t;
            while (tt >= 8 - ti) { tt -= 8 - ti; ++ti; }
            int tj = ti + tt;
            int i0 = 2*ti, i1 = i0 + 1, j0 = 2*tj, j1 = j0 + 1;
            const float2* Pi0 = reinterpret_cast<const float2*>(At + i0*SA);
            const float2* Pi1 = reinterpret_cast<const float2*>(At + i1*SA);
            const float2* Pj0 = reinterpret_cast<const float2*>(At + j0*SA);
            const float2* Pj1 = reinterpret_cast<const float2*>(At + j1*SA);
            float s00 = 0.0f, s01 = 0.0f, s10 = 0.0f, s11 = 0.0f;
#pragma unroll
            for (int g = 0; g < 32; g++) {
                float2 u0 = Pi0[g], u1 = Pi1[g], w0 = Pj0[g], w1 = Pj1[g];
                s00 = fmaf(u0.x, w0.x, s00); s00 = fmaf(u0.y, w0.y, s00);
                s01 = fmaf(u0.x, w1.x, s01); s01 = fmaf(u0.y, w1.y, s01);
                s10 = fmaf(u1.x, w0.x, s10); s10 = fmaf(u1.y, w0.y, s10);
                s11 = fmaf(u1.x, w1.x, s11); s11 = fmaf(u1.y, w1.y, s11);
            }
            sM[i0*17 + j0] = s00; sM[j0*17 + i0] = s00;
            sM[i0*17 + j1] = s01; sM[j1*17 + i0] = s01;
            sM[i1*17 + j0] = s10; sM[j0*17 + i1] = s10;
            sM[i1*17 + j1] = s11; sM[j1*17 + i1] = s11;
        }
    }
    __syncwarp();

    // ==== ONE barrier-free region: N-Gram + bn2 (throughput) overlapped with
    //      the register Cholesky (latency chain). They are independent. ====

    // ---- N = A^T Bm : 2x2 tiles over (8 i-pairs) x (8 k-pairs), zero rows skipped ----
#pragma unroll
    for (int rep = 0; rep < 2; rep++) {
        int t = lane + 32 * rep;           // 0..63, uniform tile code
        int ti = t & 7, tk = t >> 3;
        int i0 = 2*ti, i1 = i0 + 1, k0 = 2*tk, k1 = k0 + 1;
        // Bm columns are zero on gaussians 0..15 -> sum over g in [16,64)
        const float2* Pi0 = reinterpret_cast<const float2*>(At + i0*SA + 16);
        const float2* Pi1 = reinterpret_cast<const float2*>(At + i1*SA + 16);
        const float2* Qk0 = reinterpret_cast<const float2*>(Bt + k0*SA + 16);
        const float2* Qk1 = reinterpret_cast<const float2*>(Bt + k1*SA + 16);
        float s00 = 0.0f, s01 = 0.0f, s10 = 0.0f, s11 = 0.0f;
#pragma unroll
        for (int g = 0; g < 24; g++) {
            float2 u0 = Pi0[g], u1 = Pi1[g], w0 = Qk0[g], w1 = Qk1[g];
            s00 = fmaf(u0.x, w0.x, s00); s00 = fmaf(u0.y, w0.y, s00);
            s01 = fmaf(u0.x, w1.x, s01); s01 = fmaf(u0.y, w1.y, s01);
            s10 = fmaf(u1.x, w0.x, s10); s10 = fmaf(u1.y, w0.y, s10);
            s11 = fmaf(u1.x, w1.x, s11); s11 = fmaf(u1.y, w1.y, s11);
        }
        sX[k0*17 + i0] = s00; sX[k1*17 + i0] = s01;
        sX[k0*17 + i1] = s10; sX[k1*17 + i1] = s11;
    }
    // bias column k = 16 (full 64 gaussians): lanes 0..7, i-pair per lane
    if (lane < 8) {
        int i0 = 2*lane, i1 = i0 + 1;
        const float2* Pi0 = reinterpret_cast<const float2*>(At + i0*SA);
        const float2* Pi1 = reinterpret_cast<const float2*>(At + i1*SA);
        const float2* Qc  = reinterpret_cast<const float2*>(Bt + 16*SA);
        float s0 = 0.0f, s1 = 0.0f;
#pragma unroll
        for (int g = 0; g < 32; g++) {
            float2 u0 = Pi0[g], u1 = Pi1[g], w = Qc[g];
            s0 = fmaf(u0.x, w.x, s0); s0 = fmaf(u0.y, w.y, s0);
            s1 = fmaf(u1.x, w.x, s1); s1 = fmaf(u1.y, w.y, s1);
        }
        sX[16*17 + i0] = s0;
        sX[16*17 + i1] = s1;
    }

    // ---- column norms of [Bm|c] : lane k<17 owns column k ----
    float bn2 = 0.0f;
    if (lane < 17) bn2 = dot64(Bt + lane*SA, Bt + lane*SA);

    // ---- right-looking register Cholesky: lane i owns row i of M ----
    float neglog = 0.0f;
    {
        float m[16];
        int li = lane & 15;
#pragma unroll
        for (int k = 0; k < 16; k++) m[k] = sM[li*17 + k];

#pragma unroll
        for (int j = 0; j < 16; j++) {
            float d   = __shfl_sync(0xffffffffu, m[j], j);
            float Ljj = sqrtf(d);
            float rL  = __fdividef(1.0f, Ljj);
            float lij = m[j] * rL;           // L_ij on lane i (valid for i > j)
            if (lane == j) {
                neglog = -__logf(Ljj);
                sM[j*17 + 16] = rL;          // reciprocal diag for the solve
            } else if (lane > j && lane < 16) {
                sM[lane*17 + j] = lij;       // spill column j of L
            }
#pragma unroll
            for (int k = j + 1; k < 16; k++) {
                float lkj = __shfl_sync(0xffffffffu, lij, k);
                m[k] = fmaf(-lij, lkj, m[k]);
            }
        }
    }
    __syncwarp();

    // ---- solve M X = N per column (lane k<17); s_own = ||P col_k||^2 via qn ----
    float s_own = 0.0f;
    if (lane < 17) {
        float y[16];
#pragma unroll
        for (int i = 0; i < 16; i++) y[i] = sX[lane*17 + i];
        // forward: y := L^{-1} N_k  (parity-split partial sums)
#pragma unroll
        for (int i = 0; i < 16; i++) {
            float p0 = 0.0f, p1 = 0.0f;
#pragma unroll
            for (int t = 0; t < i; t++) {
                if (t & 1) p1 = fmaf(sM[i*17 + t], y[t], p1);
                else       p0 = fmaf(sM[i*17 + t], y[t], p0);
            }
            y[i] = (y[i] - (p0 + p1)) * sM[i*17 + 16];
        }
        float qn = 0.0f;
#pragma unroll
        for (int i = 0; i < 16; i++) qn = fmaf(y[i], y[i], qn);
        s_own = bn2 - qn;       // ||(I - Q1 Q1^T) col_k||^2
        // backward: y := L^{-T} y
#pragma unroll
        for (int i = 15; i >= 0; i--) {
            float p0 = 0.0f, p1 = 0.0f;
#pragma unroll
            for (int t = 15; t > i; t--) {
                if (t & 1) p1 = fmaf(sM[t*17 + i], y[t], p1);
                else       p0 = fmaf(sM[t*17 + i], y[t], p0);
            }
            y[i] = (y[i] - (p0 + p1)) * sM[i*17 + 16];
        }
#pragma unroll
        for (int i = 0; i < 16; i++) sX[lane*17 + i] = y[i];
    }
    __syncwarp();

    // ---- projection: PB = Bm - A X, Pc = c - A x_c (back into registers) ----
    float b0[16], b1[16], c0, c1;
#pragma unroll
    for (int i = 0; i < 16; i++) {
        b0[i] = Bt[i*SA + lane];
        b1[i] = Bt[i*SA + lane + 32];
    }
    c0 = Bt[16*SA + lane];
    c1 = Bt[16*SA + lane + 32];
#pragma unroll
    for (int i = 0; i < 16; i++) {
        float ai0 = At[i*SA + lane];
        float ai1 = At[i*SA + lane + 32];
#pragma unroll
        for (int k = 0; k < 16; k++) {
            float xv = sX[k*17 + i];
            b0[k] = fmaf(-ai0, xv, b0[k]);
            b1[k] = fmaf(-ai1, xv, b1[k]);
        }
        float xc = sX[16*17 + i];
        c0 = fmaf(-ai0, xc, c0);
        c1 = fmaf(-ai1, xc, c1);
    }

    float pc2 = __shfl_sync(0xffffffffu, s_own, 16);   // ||Pc||^2

    // ---- Householder QR on PB (slarfg convention), norms downdated ----
    // Trailing-column reductions processed in PAIRS (warp_sum2) to force two
    // independent SHFL chains in flight; leftover odd column pairs with c.
#pragma unroll
    for (int j = 0; j < 16; j++) {
        float sj    = __shfl_sync(0xffffffffu, s_own, j);   // ||col j rows>=j||^2
        float alpha = __shfl_sync(0xffffffffu, b0[j], j);
        sj = fmaxf(sj, 1e-30f);
        float beta = -copysignf(sqrtf(sj), alpha);
        float tau  = __fdividef(beta - alpha, beta);
        float inv  = __fdividef(1.0f, alpha - beta);

        float v0 = (lane == j) ? 1.0f : ((lane > j) ? b0[j] * inv : 0.0f);
        float v1 = b1[j] * inv;

        if (lane == j)      b0[j] = beta;
        else if (lane > j)  b0[j] = 0.0f;
        b1[j] = 0.0f;

        float xc = fmaf(v0, c0, v1 * c1);       // bias-column partial (off-chain)

        int k = j + 1;
#pragma unroll
        for (; k + 1 < 16; k += 2) {
            float xa = fmaf(v0, b0[k],   v1 * b1[k]);
            float xb = fmaf(v0, b0[k+1], v1 * b1[k+1]);
            warp_sum2(xa, xb);
            float wa = tau * xa, wb = tau * xb;
            b0[k]   = fmaf(-wa, v0, b0[k]);   b1[k]   = fmaf(-wa, v1, b1[k]);
            b0[k+1] = fmaf(-wb, v0, b0[k+1]); b1[k+1] = fmaf(-wb, v1, b1[k+1]);
            float ra = __shfl_sync(0xffffffffu, b0[k],   j);   // R_{j,k}
            float rb = __shfl_sync(0xffffffffu, b0[k+1], j);   // R_{j,k+1}
            if (lane == k)   s_own = fmaf(-ra, ra, s_own);
            if (lane == k+1) s_own = fmaf(-rb, rb, s_own);
        }
        if (k < 16) {
            // last odd trailing column paired with the bias column
            float xa = fmaf(v0, b0[k], v1 * b1[k]);
            warp_sum2(xa, xc);
            float wa = tau * xa, wc = tau * xc;
            b0[k] = fmaf(-wa, v0, b0[k]);  b1[k] = fmaf(-wa, v1, b1[k]);
            c0 = fmaf(-wc, v0, c0);        c1 = fmaf(-wc, v1, c1);
            float ra = __shfl_sync(0xffffffffu, b0[k], j);
            if (lane == k) s_own = fmaf(-ra, ra, s_own);
        } else {
            float wc = tau * warp_sum(xc);
            c0 = fmaf(-wc, v0, c0);
            c1 = fmaf(-wc, v1, c1);
        }
    }

    float lc1 = warp_sum(neglog);                       // deferred off the hot chain
    float nb2 = warp_sum((lane < 16) ? c0 * c0 : 0.0f);
    float resid = fmaxf(pc2 - nb2, 0.0f);
    float LC = lc1 - 0.5f * ((float)(PK - PH) * LOG2PI + resid);

    // ---- outputs: Next_coefs [H,BP,H] | Next_biases [H,BP] | LP_new [BP] ----
    const size_t off1 = (size_t)PH * BP * PH;
    const size_t off2 = off1 + (size_t)PH * BP;

    if (lane < 16) {
        float4* po = reinterpret_cast<float4*>(out + ((size_t)lane * BP + prob) * PH);
        po[0] = make_float4(b0[0],  b0[1],  b0[2],  b0[3]);
        po[1] = make_float4(b0[4],  b0[5],  b0[6],  b0[7]);
        po[2] = make_float4(b0[8],  b0[9],  b0[10], b0[11]);
        po[3] = make_float4(b0[12], b0[13], b0[14], b0[15]);
        out[off1 + (size_t)lane * BP + prob] = c0;
    }
    if (lane == 0) {
        out[off2 + prob] = LP[prob] + LC + Log_factors[prob];
    }
}

extern "C" void kernel_launch(void* const* d_in, const int* in_sizes, int n_in,
                              void* d_out, int out_size) {
    const float* input_i     = (const float*)d_in[0];
    const float* Prev_coefs  = (const float*)d_in[1];
    const float* Prev_biases = (const float*)d_in[2];
    const float* LP          = (const float*)d_in[3];
    const float* Log_factors = (const float*)d_in[4];
    const float* obs_var     = (const float*)d_in[5];
    const float* hid_var     = (const float*)d_in[6];
    const float* next_var    = (const float*)d_in[7];
    const float* rec_biases  = (const float*)d_in[8];

    int BP = in_sizes[3];                     // B * P (size of LP)
    int blocks = (BP + WPB - 1) / WPB;        // 1 problem per warp, 4 warps/block
    integ_kernel<<<blocks, WPB * 32>>>(input_i, Prev_coefs, Prev_biases, LP, Log_factors,
                                       obs_var, hid_var, next_var, rec_biases,
                                       (float*)d_out, BP);
}